// round 13
// baseline (speedup 1.0000x reference)
#include <cuda_runtime.h>
#include <cuda_fp16.h>
#include <cstdint>

#define NN 50000
#define EE 500000
#define D  128

// ---------------- device scratch (no allocation allowed) ----------------
__device__ float g_H[(size_t)NN * D];            // pre-conv output
__device__ float g_X[(size_t)NN * D];            // final conv output (head input)
__device__ float g_AGG[(size_t)NN * D];          // gathered neighbor sum
__device__ float g_TAIL[(size_t)NN * 32];        // [eagg(16) | deg | 0...]
__device__ float g_DEG[NN];
__device__ int   g_cnt[NN], g_cur[NN];
__device__ int   g_off[NN + 1];
__device__ int   g_srce[EE], g_eid[EE];
__device__ int   g_e64, g_q64;
// fp16 B images, fragment-paired half2 layout, 36-half (18-word) padded rows.
// chunk = 32 k's; half index = n*36 + (k&31); pads 32..35 stay zero (BSS).
__device__ uint16_t g_Bpre16[2][4 * 4608];    // K=128 -> 4 chunks
__device__ uint16_t g_Bpost16[2][9 * 4608];   // K=288 -> 9 chunks

// ---------------- helpers ----------------
// pack {lo=x, hi=y} as fp16x2 (one SASS instr)
__device__ __forceinline__ uint32_t f2h2(float2 v) {
    uint32_t o;
    asm("cvt.rn.f16x2.f32 %0, %1, %2;" : "=r"(o) : "f"(v.y), "f"(v.x));
    return o;
}
__device__ __forceinline__ void mma_f16(float* c, uint32_t a0, uint32_t a1,
                                        uint32_t a2, uint32_t a3,
                                        uint32_t b0, uint32_t b1) {
    asm volatile(
        "mma.sync.aligned.m16n8k16.row.col.f32.f16.f16.f32 "
        "{%0,%1,%2,%3}, {%4,%5,%6,%7}, {%8,%9}, {%0,%1,%2,%3};"
        : "+f"(c[0]), "+f"(c[1]), "+f"(c[2]), "+f"(c[3])
        : "r"(a0), "r"(a1), "r"(a2), "r"(a3), "r"(b0), "r"(b1));
}
__device__ __forceinline__ void cpa16(uint32_t dst, const void* src, int sz) {
    asm volatile("cp.async.cg.shared.global [%0], [%1], 16, %2;"
                 :: "r"(dst), "l"(src), "r"(sz) : "memory");
}
#define CP_COMMIT() asm volatile("cp.async.commit_group;" ::: "memory")
#define CP_WAIT1()  asm volatile("cp.async.wait_group 1;" ::: "memory")

// ---------------- fused detect (warp-parallel) + zero ----------------
__global__ void detect_zero_kernel(const int* __restrict__ ei, const int* __restrict__ eli, int n) {
    int i = blockIdx.x * blockDim.x + threadIdx.x;
    if (i < n) { g_cnt[i] = 0; g_cur[i] = 0; }
    if (blockIdx.x == 0 && threadIdx.x < 32) {
        int lane = threadIdx.x;
        int a = 0, b = 0;
        #pragma unroll
        for (int j = 0; j < 4; j++) {
            a |= ei[2 * (lane * 4 + j) + 1];
            b |= eli[2 * (lane * 4 + j) + 1];
        }
        unsigned ba = __ballot_sync(0xffffffffu, a != 0);
        unsigned bb = __ballot_sync(0xffffffffu, b != 0);
        if (lane == 0) {
            g_e64 = (ba == 0) ? 1 : 0;
            g_q64 = (bb == 0) ? 1 : 0;
        }
    }
}

// ---------------- fused B-image prep (fp16) ----------------
__device__ __forceinline__ void prep_one(const float* W, const float* bias,
                                         uint16_t* img, int K_eff, int idx) {
    int n = idx & 127;
    int k = idx >> 7;
    float v = 0.f;
    if (k < K_eff) v = W[(size_t)k * 128 + n];
    else if (k == K_eff && bias != nullptr) v = bias[n];
    __half h = __float2half_rn(v);
    img[(size_t)(k >> 5) * 4608 + n * 36 + (k & 31)] = *(uint16_t*)&h;
}
__global__ void prep_all_kernel(const float* W1, const float* W2,
                                const float* W3, const float* b3,
                                const float* W4, const float* b4,
                                uint16_t* img1, uint16_t* img2,
                                uint16_t* img3, uint16_t* img4) {
    int idx = blockIdx.x * blockDim.x + threadIdx.x;
    if (idx < 16384)       prep_one(W1, nullptr, img1, 128, idx);
    else if (idx < 32768)  prep_one(W2, nullptr, img2, 128, idx - 16384);
    else if (idx < 69632)  prep_one(W3, b3, img3, 272, idx - 32768);
    else if (idx < 106496) prep_one(W4, b4, img4, 272, idx - 69632);
}

// ---------------- CSR build ----------------
__global__ void hist_kernel(const void* __restrict__ ei, int E) {
    int e = blockIdx.x * blockDim.x + threadIdx.x;
    if (e >= E) return;
    int d = g_e64 ? (int)((const long long*)ei)[(size_t)E + e] : ((const int*)ei)[(size_t)E + e];
    atomicAdd(&g_cnt[d], 1);
}
// Single-block fused scan: g_off = exclusive_scan(g_cnt), g_DEG = float(g_cnt).
__global__ __launch_bounds__(1024)
void scan_fused_kernel(int n, int E) {
    __shared__ int wsum[32];
    const int tid = threadIdx.x, lane = tid & 31, wid = tid >> 5;
    const int vpt = (n + 1023) >> 10;
    const int start = tid * vpt;
    const int end = (start + vpt < n) ? (start + vpt) : n;
    if (tid == 0) g_off[n] = E;
    int sum = 0;
    for (int i = start; i < end; i++) sum += g_cnt[i];
    int x = sum;
    #pragma unroll
    for (int o = 1; o < 32; o <<= 1) {
        int t = __shfl_up_sync(0xffffffffu, x, o);
        if (lane >= o) x += t;
    }
    if (lane == 31) wsum[wid] = x;
    __syncthreads();
    if (wid == 0) {
        int s = wsum[lane];
        #pragma unroll
        for (int o = 1; o < 32; o <<= 1) {
            int t = __shfl_up_sync(0xffffffffu, s, o);
            if (lane >= o) s += t;
        }
        wsum[lane] = s;
    }
    __syncthreads();
    int run = ((wid > 0) ? wsum[wid - 1] : 0) + x - sum;   // exclusive base
    for (int i = start; i < end; i++) {
        int c = g_cnt[i];
        g_off[i] = run;
        g_DEG[i] = (float)c;
        run += c;
    }
}
__global__ void fill_kernel(const void* __restrict__ ei, int E) {
    int e = blockIdx.x * blockDim.x + threadIdx.x;
    if (e >= E) return;
    int s, d;
    if (g_e64) {
        s = (int)((const long long*)ei)[e];
        d = (int)((const long long*)ei)[(size_t)E + e];
    } else {
        s = ((const int*)ei)[e];
        d = ((const int*)ei)[(size_t)E + e];
    }
    int pos = g_off[d] + atomicAdd(&g_cur[d], 1);
    g_srce[pos] = s;
    g_eid[pos]  = e;
}
// eagg + TAIL pack: TAIL[w][0..15]=eagg, [16]=deg, [17..31]=0
__global__ __launch_bounds__(256)
void eagg_tail_kernel(const float* __restrict__ ef, int n) {
    int w = (blockIdx.x * blockDim.x + threadIdx.x) >> 5;
    int lane = threadIdx.x & 31;
    if (w >= n) return;
    int rs = g_off[w], re = g_off[w + 1];
    float acc = 0.f;
    if (lane < 16) {
        for (int j = rs; j < re; j++) {
            int e = __ldg(&g_eid[j]);
            acc += __ldg(ef + (size_t)e * 16 + lane);
        }
    } else if (lane == 16) {
        acc = g_DEG[w];
    }
    g_TAIL[(size_t)w * 32 + lane] = acc;
}

// ---------------- aggregation gather (atomic-free) ----------
__global__ __launch_bounds__(256)
void gather_agg_kernel(const float* __restrict__ H, int n) {
    int w = (blockIdx.x * blockDim.x + threadIdx.x) >> 5;
    int lane = threadIdx.x & 31;
    if (w >= n) return;
    int rs = g_off[w], re = g_off[w + 1];
    float4 a0 = make_float4(0.f, 0.f, 0.f, 0.f);
    float4 a1 = make_float4(0.f, 0.f, 0.f, 0.f);
    const float* base = H + (size_t)lane * 4;
    int j = rs;
    for (; j + 1 < re; j += 2) {
        int s0 = __ldg(&g_srce[j]), s1 = __ldg(&g_srce[j + 1]);
        float4 v0 = *(const float4*)(base + (size_t)s0 * 128);
        float4 v1 = *(const float4*)(base + (size_t)s1 * 128);
        a0.x += v0.x; a0.y += v0.y; a0.z += v0.z; a0.w += v0.w;
        a1.x += v1.x; a1.y += v1.y; a1.z += v1.z; a1.w += v1.w;
    }
    if (j < re) {
        int s0 = __ldg(&g_srce[j]);
        float4 v0 = *(const float4*)(base + (size_t)s0 * 128);
        a0.x += v0.x; a0.y += v0.y; a0.z += v0.z; a0.w += v0.w;
    }
    a0.x += a1.x; a0.y += a1.y; a0.z += a1.z; a0.w += a1.w;
    *(float4*)(g_AGG + (size_t)w * 128 + lane * 4) = a0;
}

// ---------------- fp16 mma GEMM, cp.async double-buffered ----------------
// SMEM (floats): Asb0 [0,4608) Asb1 [4608,9216), then B halves region:
//   Bs0 at float-offset 9216 (2304 words), Bs1 at 11520. GSMEM = 13824*4.
#define GSMEM (13824 * 4)                            // 55296 B
#define FSMEM ((13824 + 128 * 132) * 4)              // 122880 B (+ fp32 X tile)

// MODE 0: plain A (K=128), bias+relu epilogue.
// MODE 1: stitched K=288 from A|AGG|TAIL, deg-scale after chunk 3, RELU.
// MODE 2: same as MODE 1 but NO relu (final layer).
template <int MODE>
__device__ __forceinline__ void stage_chunk(const float* __restrict__ A,
                                            const uint16_t* __restrict__ Bimg,
                                            float* AsBuf, uint32_t* BsBuf,
                                            int c, int block_row, int n, int tid) {
    const int k0 = c * 32;
    const float* srcbase;
    int stride, off;
    if (MODE == 0)      { srcbase = A;      stride = 128; off = k0; }
    else if (k0 < 128)  { srcbase = A;      stride = 128; off = k0; }
    else if (k0 < 256)  { srcbase = g_AGG;  stride = 128; off = k0 - 128; }
    else                { srcbase = g_TAIL; stride = 32;  off = 0; }
    #pragma unroll
    for (int l = 0; l < 4; l++) {
        int i = tid + l * 256;                 // 1024 = 128 rows x 8 float4
        int r = i >> 3, kq = (i & 7) << 2;
        int grow = block_row + r;
        uint32_t dst = (uint32_t)__cvta_generic_to_shared(AsBuf + r * 36 + kq);
        cpa16(dst, srcbase + (size_t)grow * stride + off + kq, grow < n ? 16 : 0);
    }
    // B chunk: 4608 halves = 9216 B = 576 x 16B
    const float4* bsrc = (const float4*)(Bimg + (size_t)c * 4608);
    #pragma unroll
    for (int l = 0; l < 3; l++) {
        int i = tid + l * 256;
        if (i < 576) {
            uint32_t dst = (uint32_t)__cvta_generic_to_shared((float4*)BsBuf + i);
            cpa16(dst, bsrc + i, 16);
        }
    }
}
__device__ __forceinline__ void stage_b_only(const uint16_t* __restrict__ Bimg,
                                             uint32_t* BsBuf, int c, int tid) {
    const float4* bsrc = (const float4*)(Bimg + (size_t)c * 4608);
    #pragma unroll
    for (int l = 0; l < 3; l++) {
        int i = tid + l * 256;
        if (i < 576) {
            uint32_t dst = (uint32_t)__cvta_generic_to_shared((float4*)BsBuf + i);
            cpa16(dst, bsrc + i, 16);
        }
    }
}

// One 32-k chunk: 2 x m16n8k16 steps. A read fp32 from SMEM (convert at load);
// B read directly as packed half2 words (word j = {B[2j][n], B[2j+1][n]}).
__device__ __forceinline__ void mma_chunk(float acc[4][4][4], const float* Asrc,
                                          int astride, int akoff, const uint32_t* Bs,
                                          int wr, int wc, int g, int tg) {
    #pragma unroll
    for (int ks = 0; ks < 2; ks++) {
        const int kb = akoff + ks * 16;
        uint32_t bfr[4][2];
        #pragma unroll
        for (int u = 0; u < 4; u++) {
            const int nn = wc + u * 8 + g;
            bfr[u][0] = Bs[nn * 18 + ks * 8 + tg];       // k = 2tg, 2tg+1
            bfr[u][1] = Bs[nn * 18 + ks * 8 + tg + 4];   // k = 2tg+8, 2tg+9
        }
        #pragma unroll
        for (int t = 0; t < 4; t++) {
            const int r0 = wr + t * 16 + g, r1 = r0 + 8;
            float2 x0 = *(const float2*)&Asrc[r0 * astride + kb + 2 * tg];
            float2 x1 = *(const float2*)&Asrc[r1 * astride + kb + 2 * tg];
            float2 x2 = *(const float2*)&Asrc[r0 * astride + kb + 2 * tg + 8];
            float2 x3 = *(const float2*)&Asrc[r1 * astride + kb + 2 * tg + 8];
            uint32_t a0 = f2h2(x0), a1 = f2h2(x1), a2 = f2h2(x2), a3 = f2h2(x3);
            #pragma unroll
            for (int u = 0; u < 4; u++)
                mma_f16(acc[t][u], a0, a1, a2, a3, bfr[u][0], bfr[u][1]);
        }
    }
}

// deg*(H·Wi) == (deg⊙H)·Wi  (row scaling commutes with right-multiplication)
__device__ __forceinline__ void scale_acc_deg(float acc[4][4][4], int block_row,
                                              int wr, int g, int n) {
    #pragma unroll
    for (int t = 0; t < 4; t++) {
        const int r0 = block_row + wr + t * 16 + g, r1 = r0 + 8;
        const float d0 = (r0 < n) ? g_DEG[r0] : 0.f;
        const float d1 = (r1 < n) ? g_DEG[r1] : 0.f;
        #pragma unroll
        for (int u = 0; u < 4; u++) {
            acc[t][u][0] *= d0; acc[t][u][1] *= d0;
            acc[t][u][2] *= d1; acc[t][u][3] *= d1;
        }
    }
}

template <int MODE>
__global__ __launch_bounds__(256, 2)
void gemm_mma_kernel(const float* __restrict__ A, const uint16_t* __restrict__ Bimg,
                     const float* __restrict__ bias, float* __restrict__ Cout, int n) {
    extern __shared__ __align__(16) float sm[];
    float* Asb[2] = { sm, sm + 4608 };
    uint32_t* Bsb[2] = { (uint32_t*)(sm + 9216), (uint32_t*)(sm + 11520) };
    const int tid = threadIdx.x, lane = tid & 31, wid = tid >> 5;
    const int g = lane >> 2, tg = lane & 3;
    const int wr = (wid & 1) * 64, wc = (wid >> 1) * 32;
    const int block_row = blockIdx.x * 128;
    const int CHUNKS = (MODE == 0) ? 4 : 9;

    float acc[4][4][4];
    #pragma unroll
    for (int t = 0; t < 4; t++)
        #pragma unroll
        for (int u = 0; u < 4; u++)
            #pragma unroll
            for (int v = 0; v < 4; v++) acc[t][u][v] = 0.f;

    stage_chunk<MODE>(A, Bimg, Asb[0], Bsb[0], 0, block_row, n, tid);
    CP_COMMIT();

    for (int c = 0; c < CHUNKS; c++) {
        const int cur = c & 1;
        if (c + 1 < CHUNKS)
            stage_chunk<MODE>(A, Bimg, Asb[(c + 1) & 1], Bsb[(c + 1) & 1],
                              c + 1, block_row, n, tid);
        CP_COMMIT();
        CP_WAIT1();
        __syncthreads();
        mma_chunk(acc, Asb[cur], 36, 0, Bsb[cur], wr, wc, g, tg);
        if (MODE != 0 && c == 3)             // end of H*Wi chunks -> apply deg
            scale_acc_deg(acc, block_row, wr, g, n);
        __syncthreads();
    }
    // ---- epilogue ----
    #pragma unroll
    for (int t = 0; t < 4; t++) {
        const int r0 = block_row + wr + t * 16 + g, r1 = r0 + 8;
        #pragma unroll
        for (int u = 0; u < 4; u++) {
            const int col = wc + u * 8 + tg * 2;
            float2 v0 = make_float2(acc[t][u][0], acc[t][u][1]);
            float2 v1 = make_float2(acc[t][u][2], acc[t][u][3]);
            if (MODE == 0) {
                float2 b2 = *(const float2*)(bias + col);
                v0.x = fmaxf(v0.x + b2.x, 0.f); v0.y = fmaxf(v0.y + b2.y, 0.f);
                v1.x = fmaxf(v1.x + b2.x, 0.f); v1.y = fmaxf(v1.y + b2.y, 0.f);
            } else if (MODE == 1) {
                v0.x = fmaxf(v0.x, 0.f); v0.y = fmaxf(v0.y, 0.f);
                v1.x = fmaxf(v1.x, 0.f); v1.y = fmaxf(v1.y, 0.f);
            }
            // MODE 2: raw accumulator (final layer, no relu)
            if (r0 < n) *(float2*)(Cout + (size_t)r0 * 128 + col) = v0;
            if (r1 < n) *(float2*)(Cout + (size_t)r1 * 128 + col) = v1;
        }
    }
}

// ---------------- FUSED: postGEMM layer1 + preGEMM layer2 ----
__global__ __launch_bounds__(256)
void gemm_fused_kernel(const float* __restrict__ Hin,
                       const uint16_t* __restrict__ Bimg1, const uint16_t* __restrict__ Bimg2,
                       const float* __restrict__ bias2, float* __restrict__ Hout, int n) {
    extern __shared__ __align__(16) float sm[];
    float* Asb[2] = { sm, sm + 4608 };
    uint32_t* Bsb[2] = { (uint32_t*)(sm + 9216), (uint32_t*)(sm + 11520) };
    float* Xt = sm + 13824;                 // 128 x 132 fp32 X tile
    const int tid = threadIdx.x, lane = tid & 31, wid = tid >> 5;
    const int g = lane >> 2, tg = lane & 3;
    const int wr = (wid & 1) * 64, wc = (wid >> 1) * 32;
    const int block_row = blockIdx.x * 128;

    float acc[4][4][4];
    #pragma unroll
    for (int t = 0; t < 4; t++)
        #pragma unroll
        for (int u = 0; u < 4; u++)
            #pragma unroll
            for (int v = 0; v < 4; v++) acc[t][u][v] = 0.f;

    // ================= GEMM 1 (stitched K=288) =================
    stage_chunk<1>(Hin, Bimg1, Asb[0], Bsb[0], 0, block_row, n, tid);
    CP_COMMIT();
    for (int c = 0; c < 9; c++) {
        const int cur = c & 1;
        if (c + 1 < 9)
            stage_chunk<1>(Hin, Bimg1, Asb[(c + 1) & 1], Bsb[(c + 1) & 1],
                           c + 1, block_row, n, tid);
        CP_COMMIT();
        CP_WAIT1();
        __syncthreads();
        mma_chunk(acc, Asb[cur], 36, 0, Bsb[cur], wr, wc, g, tg);
        if (c == 3)
            scale_acc_deg(acc, block_row, wr, g, n);
        __syncthreads();
    }
    // prefetch GEMM2's first B chunk while writing the X tile
    stage_b_only(Bimg2, Bsb[0], 0, tid);
    CP_COMMIT();
    // epilogue1 -> X tile (relu)
    #pragma unroll
    for (int t = 0; t < 4; t++) {
        const int r0 = wr + t * 16 + g, r1 = r0 + 8;
        #pragma unroll
        for (int u = 0; u < 4; u++) {
            const int col = wc + u * 8 + tg * 2;
            float2 v0 = make_float2(fmaxf(acc[t][u][0], 0.f), fmaxf(acc[t][u][1], 0.f));
            float2 v1 = make_float2(fmaxf(acc[t][u][2], 0.f), fmaxf(acc[t][u][3], 0.f));
            *(float2*)&Xt[r0 * 132 + col] = v0;
            *(float2*)&Xt[r1 * 132 + col] = v1;
        }
    }
    // ================= GEMM 2 (on X tile) =================
    #pragma unroll
    for (int t = 0; t < 4; t++)
        #pragma unroll
        for (int u = 0; u < 4; u++)
            #pragma unroll
            for (int v = 0; v < 4; v++) acc[t][u][v] = 0.f;
    __syncthreads();                        // X tile visible to all warps
    for (int c = 0; c < 4; c++) {
        const int cur = c & 1;
        if (c + 1 < 4)
            stage_b_only(Bimg2, Bsb[(c + 1) & 1], c + 1, tid);
        CP_COMMIT();
        CP_WAIT1();
        __syncthreads();
        mma_chunk(acc, Xt, 132, c * 32, Bsb[cur], wr, wc, g, tg);
        __syncthreads();
    }
    // epilogue2: relu(acc + bias2) -> g_H
    #pragma unroll
    for (int t = 0; t < 4; t++) {
        const int r0 = block_row + wr + t * 16 + g, r1 = r0 + 8;
        #pragma unroll
        for (int u = 0; u < 4; u++) {
            const int col = wc + u * 8 + tg * 2;
            float2 b2 = *(const float2*)(bias2 + col);
            float2 v0, v1;
            v0.x = fmaxf(acc[t][u][0] + b2.x, 0.f); v0.y = fmaxf(acc[t][u][1] + b2.y, 0.f);
            v1.x = fmaxf(acc[t][u][2] + b2.x, 0.f); v1.y = fmaxf(acc[t][u][3] + b2.y, 0.f);
            if (r0 < n) *(float2*)(Hout + (size_t)r0 * 128 + col) = v0;
            if (r1 < n) *(float2*)(Hout + (size_t)r1 * 128 + col) = v1;
        }
    }
}

// ---------------- link-prediction head ----------------
__global__ __launch_bounds__(256)
void head_kernel(const float* __restrict__ X, const void* __restrict__ eli,
                 const float* __restrict__ lpW, const float* __restrict__ lpb,
                 float* __restrict__ out, int Q) {
    int w = (blockIdx.x * blockDim.x + threadIdx.x) >> 5;
    int lane = threadIdx.x & 31;
    if (w >= Q) return;
    float2 wa[4], wb[4];
    #pragma unroll
    for (int i = 0; i < 4; i++) {
        wa[i] = *(const float2*)(lpW + (size_t)(4 * lane + i) * 2);
        wb[i] = *(const float2*)(lpW + (size_t)(128 + 4 * lane + i) * 2);
    }
    int i0 = 0, i1 = 0;
    if (lane == 0) {
        if (g_q64) {
            i0 = (int)((const long long*)eli)[w];
            i1 = (int)((const long long*)eli)[(size_t)Q + w];
        } else {
            i0 = ((const int*)eli)[w];
            i1 = ((const int*)eli)[(size_t)Q + w];
        }
    }
    i0 = __shfl_sync(0xffffffffu, i0, 0);
    i1 = __shfl_sync(0xffffffffu, i1, 0);
    float4 a = *(const float4*)(X + (size_t)i0 * 128 + lane * 4);
    float4 b = *(const float4*)(X + (size_t)i1 * 128 + lane * 4);
    float p0 = a.x * wa[0].x + a.y * wa[1].x + a.z * wa[2].x + a.w * wa[3].x
             + b.x * wb[0].x + b.y * wb[1].x + b.z * wb[2].x + b.w * wb[3].x;
    float p1 = a.x * wa[0].y + a.y * wa[1].y + a.z * wa[2].y + a.w * wa[3].y
             + b.x * wb[0].y + b.y * wb[1].y + b.z * wb[2].y + b.w * wb[3].y;
    #pragma unroll
    for (int off = 16; off; off >>= 1) {
        p0 += __shfl_down_sync(0xffffffffu, p0, off);
        p1 += __shfl_down_sync(0xffffffffu, p1, off);
    }
    if (lane == 0) {
        out[(size_t)2 * w + 0] = p0 + lpb[0];
        out[(size_t)2 * w + 1] = p1 + lpb[1];
    }
}

// ---------------- launch ----------------
extern "C" void kernel_launch(void* const* d_in, const int* in_sizes, int n_in,
                              void* d_out, int out_size) {
    const float* node_feature = (const float*)d_in[0];
    const void*  edge_index   = d_in[1];
    const float* edge_feature = (const float*)d_in[2];
    const void*  eli          = d_in[3];
    const float* c1_pre_W = (const float*)d_in[4];
    const float* c1_pre_b = (const float*)d_in[5];
    const float* c1_msg_W = (const float*)d_in[6];
    const float* c1_msg_b = (const float*)d_in[7];
    const float* c2_pre_W = (const float*)d_in[8];
    const float* c2_pre_b = (const float*)d_in[9];
    const float* c2_msg_W = (const float*)d_in[10];
    const float* c2_msg_b = (const float*)d_in[11];
    const float* lp_W     = (const float*)d_in[12];
    const float* lp_b     = (const float*)d_in[13];
    float* out = (float*)d_out;

    const int N = in_sizes[0] / D;
    const int E = in_sizes[1] / 2;
    const int Q = in_sizes[3] / 2;

    float *H, *X;
    uint16_t *Bpre, *Bpost;
    cudaGetSymbolAddress((void**)&H,  g_H);
    cudaGetSymbolAddress((void**)&X,  g_X);
    cudaGetSymbolAddress((void**)&Bpre, g_Bpre16);
    cudaGetSymbolAddress((void**)&Bpost, g_Bpost16);
    uint16_t* Bpre1  = Bpre;
    uint16_t* Bpre2  = Bpre + 4 * 4608;
    uint16_t* Bpost1 = Bpost;
    uint16_t* Bpost2 = Bpost + 9 * 4608;

    static int init_done = 0;
    static cudaStream_t s2;
    static cudaEvent_t evF, evFill, evEagg;
    if (!init_done) {
        cudaFuncSetAttribute(gemm_mma_kernel<0>, cudaFuncAttributeMaxDynamicSharedMemorySize, GSMEM);
        cudaFuncSetAttribute(gemm_mma_kernel<2>, cudaFuncAttributeMaxDynamicSharedMemorySize, GSMEM);
        cudaFuncSetAttribute(gemm_fused_kernel, cudaFuncAttributeMaxDynamicSharedMemorySize, FSMEM);
        cudaStreamCreateWithFlags(&s2, cudaStreamNonBlocking);
        cudaEventCreateWithFlags(&evF, cudaEventDisableTiming);
        cudaEventCreateWithFlags(&evFill, cudaEventDisableTiming);
        cudaEventCreateWithFlags(&evEagg, cudaEventDisableTiming);
        init_done = 1;
    }

    const int gemm_blocks  = (N + 127) / 128;
    const int warp8_blocks = (N + 7) / 8;
    const int edge_blocks  = (E + 255) / 256;
    const int nb = (N + 255) / 256;

    // root: zero counters + dtype detect
    detect_zero_kernel<<<nb, 256>>>((const int*)edge_index, (const int*)eli, N);

    // ---- fork: CSR build on side stream ----
    cudaEventRecord(evF, 0);
    cudaStreamWaitEvent(s2, evF, 0);
    hist_kernel<<<edge_blocks, 256, 0, s2>>>(edge_index, E);
    scan_fused_kernel<<<1, 1024, 0, s2>>>(N, E);
    fill_kernel<<<edge_blocks, 256, 0, s2>>>(edge_index, E);
    cudaEventRecord(evFill, s2);
    eagg_tail_kernel<<<warp8_blocks, 256, 0, s2>>>(edge_feature, N);   // concurrent with gather
    cudaEventRecord(evEagg, s2);

    // ---- main stream: weight prep + layer-1 pre-GEMM ----
    prep_all_kernel<<<(106496 + 255) / 256, 256>>>(c1_pre_W, c2_pre_W,
                                                   c1_msg_W, c1_msg_b,
                                                   c2_msg_W, c2_msg_b,
                                                   Bpre1, Bpre2, Bpost1, Bpost2);
    gemm_mma_kernel<0><<<gemm_blocks, 256, GSMEM>>>(node_feature, Bpre1, c1_pre_b, H, N);

    // ---- join 1: CSR arrays ready -> gather (concurrent with eagg on s2) ----
    cudaStreamWaitEvent(0, evFill, 0);
    gather_agg_kernel<<<warp8_blocks, 256>>>(H, N);

    // ---- join 2: TAIL ready -> fused postGEMM1 + preGEMM2 (H overwritten) ----
    cudaStreamWaitEvent(0, evEagg, 0);
    gemm_fused_kernel<<<gemm_blocks, 256, FSMEM>>>(H, Bpost1, Bpre2, c2_pre_b, H, N);

    // layer 2 rest (MODE 2: stitched, NO relu — final output)
    gather_agg_kernel<<<warp8_blocks, 256>>>(H, N);
    gemm_mma_kernel<2><<<gemm_blocks, 256, GSMEM>>>(H, Bpost2, nullptr, X, N);

    head_kernel<<<(Q + 7) / 8, 256>>>(X, eli, lp_W, lp_b, out, Q);
}

// round 14
// speedup vs baseline: 1.4053x; 1.4053x over previous
#include <cuda_runtime.h>
#include <cuda_fp16.h>
#include <cstdint>

#define NN 50000
#define EE 500000
#define D  128

// ---------------- device scratch (no allocation allowed) ----------------
__device__ float g_H[(size_t)NN * D];            // pre-conv output
__device__ float g_X[(size_t)NN * D];            // final conv output (head input)
__device__ float g_AGG[(size_t)NN * D];          // gathered neighbor sum
__device__ float g_TAIL[(size_t)NN * 32];        // [eagg(16) | deg | 0...]
__device__ float g_DEG[NN];
__device__ int   g_cnt[NN], g_cur[NN];
__device__ int   g_off[NN + 1];
__device__ int   g_srce[EE], g_eid[EE];
__device__ int   g_bsum[512], g_bsum2[512];
__device__ int   g_e64, g_q64;
// fp16 B images, fragment-paired half2 layout, 36-half (18-word) padded rows.
// chunk = 32 k's; half index = n*36 + (k&31); pads 32..35 stay zero (BSS).
__device__ uint16_t g_Bpre16[2][4 * 4608];    // K=128 -> 4 chunks
__device__ uint16_t g_Bpost16[2][9 * 4608];   // K=288 -> 9 chunks

// ---------------- helpers ----------------
// pack {lo=x, hi=y} as fp16x2 (one SASS instr)
__device__ __forceinline__ uint32_t f2h2(float2 v) {
    uint32_t o;
    asm("cvt.rn.f16x2.f32 %0, %1, %2;" : "=r"(o) : "f"(v.y), "f"(v.x));
    return o;
}
__device__ __forceinline__ void mma_f16(float* c, uint32_t a0, uint32_t a1,
                                        uint32_t a2, uint32_t a3,
                                        uint32_t b0, uint32_t b1) {
    asm volatile(
        "mma.sync.aligned.m16n8k16.row.col.f32.f16.f16.f32 "
        "{%0,%1,%2,%3}, {%4,%5,%6,%7}, {%8,%9}, {%0,%1,%2,%3};"
        : "+f"(c[0]), "+f"(c[1]), "+f"(c[2]), "+f"(c[3])
        : "r"(a0), "r"(a1), "r"(a2), "r"(a3), "r"(b0), "r"(b1));
}
__device__ __forceinline__ void cpa16(uint32_t dst, const void* src, int sz) {
    asm volatile("cp.async.cg.shared.global [%0], [%1], 16, %2;"
                 :: "r"(dst), "l"(src), "r"(sz) : "memory");
}
#define CP_COMMIT() asm volatile("cp.async.commit_group;" ::: "memory")
#define CP_WAIT1()  asm volatile("cp.async.wait_group 1;" ::: "memory")

// ---------------- fused detect (warp-parallel) + zero ----------------
__global__ void detect_zero_kernel(const int* __restrict__ ei, const int* __restrict__ eli, int n) {
    int i = blockIdx.x * blockDim.x + threadIdx.x;
    if (i < n) { g_cnt[i] = 0; g_cur[i] = 0; }
    if (blockIdx.x == 0 && threadIdx.x < 32) {
        int lane = threadIdx.x;
        int a = 0, b = 0;
        #pragma unroll
        for (int j = 0; j < 4; j++) {
            a |= ei[2 * (lane * 4 + j) + 1];
            b |= eli[2 * (lane * 4 + j) + 1];
        }
        unsigned ba = __ballot_sync(0xffffffffu, a != 0);
        unsigned bb = __ballot_sync(0xffffffffu, b != 0);
        if (lane == 0) {
            g_e64 = (ba == 0) ? 1 : 0;
            g_q64 = (bb == 0) ? 1 : 0;
        }
    }
}

// ---------------- fused B-image prep (fp16) ----------------
__device__ __forceinline__ void prep_one(const float* W, const float* bias,
                                         uint16_t* img, int K_eff, int idx) {
    int n = idx & 127;
    int k = idx >> 7;
    float v = 0.f;
    if (k < K_eff) v = W[(size_t)k * 128 + n];
    else if (k == K_eff && bias != nullptr) v = bias[n];
    __half h = __float2half_rn(v);
    img[(size_t)(k >> 5) * 4608 + n * 36 + (k & 31)] = *(uint16_t*)&h;
}
__global__ void prep_all_kernel(const float* W1, const float* W2,
                                const float* W3, const float* b3,
                                const float* W4, const float* b4,
                                uint16_t* img1, uint16_t* img2,
                                uint16_t* img3, uint16_t* img4) {
    int idx = blockIdx.x * blockDim.x + threadIdx.x;
    if (idx < 16384)       prep_one(W1, nullptr, img1, 128, idx);
    else if (idx < 32768)  prep_one(W2, nullptr, img2, 128, idx - 16384);
    else if (idx < 69632)  prep_one(W3, b3, img3, 272, idx - 32768);
    else if (idx < 106496) prep_one(W4, b4, img4, 272, idx - 69632);
}

// ---------------- CSR build ----------------
__global__ void hist_kernel(const void* __restrict__ ei, int E) {
    int e = blockIdx.x * blockDim.x + threadIdx.x;
    if (e >= E) return;
    int d = g_e64 ? (int)((const long long*)ei)[(size_t)E + e] : ((const int*)ei)[(size_t)E + e];
    atomicAdd(&g_cnt[d], 1);
}
__global__ void scan1_kernel(int n) {
    __shared__ int s[256];
    int idx = blockIdx.x * 256 + threadIdx.x;
    int v = (idx < n) ? g_cnt[idx] : 0;
    s[threadIdx.x] = v; __syncthreads();
    #pragma unroll
    for (int o = 1; o < 256; o <<= 1) {
        int t = (threadIdx.x >= o) ? s[threadIdx.x - o] : 0;
        __syncthreads(); s[threadIdx.x] += t; __syncthreads();
    }
    if (idx < n) g_off[idx] = s[threadIdx.x] - v;
    if (threadIdx.x == 255) g_bsum[blockIdx.x] = s[255];
}
// Warp-shuffle scan of up to 512 block sums (512 threads, 1 block).
__global__ void scan2_kernel(int nb) {
    __shared__ int wsum[16];
    int tid = threadIdx.x;            // 0..511
    int lane = tid & 31, wid = tid >> 5;
    int v = (tid < nb) ? g_bsum[tid] : 0;
    int x = v;
    #pragma unroll
    for (int o = 1; o < 32; o <<= 1) {
        int t = __shfl_up_sync(0xffffffffu, x, o);
        if (lane >= o) x += t;
    }
    if (lane == 31) wsum[wid] = x;
    __syncthreads();
    if (wid == 0) {
        int s = (lane < 16) ? wsum[lane] : 0;
        #pragma unroll
        for (int o = 1; o < 16; o <<= 1) {
            int t = __shfl_up_sync(0xffffffffu, s, o);
            if (lane >= o) s += t;
        }
        if (lane < 16) wsum[lane] = s;
    }
    __syncthreads();
    int base = (wid > 0) ? wsum[wid - 1] : 0;
    g_bsum2[tid] = base + x - v;      // exclusive
}
__global__ void scan3_kernel(int n, int E) {
    int idx = blockIdx.x * blockDim.x + threadIdx.x;
    if (idx < n) {
        g_off[idx] += g_bsum2[idx >> 8];
        g_DEG[idx] = (float)g_cnt[idx];
    }
    if (idx == n) g_off[n] = E;
}
__global__ void fill_kernel(const void* __restrict__ ei, int E) {
    int e = blockIdx.x * blockDim.x + threadIdx.x;
    if (e >= E) return;
    int s, d;
    if (g_e64) {
        s = (int)((const long long*)ei)[e];
        d = (int)((const long long*)ei)[(size_t)E + e];
    } else {
        s = ((const int*)ei)[e];
        d = ((const int*)ei)[(size_t)E + e];
    }
    int pos = g_off[d] + atomicAdd(&g_cur[d], 1);
    g_srce[pos] = s;
    g_eid[pos]  = e;
}
// eagg + TAIL pack: TAIL[w][0..15]=eagg, [16]=deg, [17..31]=0
__global__ __launch_bounds__(256)
void eagg_tail_kernel(const float* __restrict__ ef, int n) {
    int w = (blockIdx.x * blockDim.x + threadIdx.x) >> 5;
    int lane = threadIdx.x & 31;
    if (w >= n) return;
    int rs = g_off[w], re = g_off[w + 1];
    float acc = 0.f;
    if (lane < 16) {
        for (int j = rs; j < re; j++) {
            int e = __ldg(&g_eid[j]);
            acc += __ldg(ef + (size_t)e * 16 + lane);
        }
    } else if (lane == 16) {
        acc = g_DEG[w];
    }
    g_TAIL[(size_t)w * 32 + lane] = acc;
}

// ---------------- aggregation gather (atomic-free) ----------
__global__ __launch_bounds__(256)
void gather_agg_kernel(const float* __restrict__ H, int n) {
    int w = (blockIdx.x * blockDim.x + threadIdx.x) >> 5;
    int lane = threadIdx.x & 31;
    if (w >= n) return;
    int rs = g_off[w], re = g_off[w + 1];
    float4 a0 = make_float4(0.f, 0.f, 0.f, 0.f);
    float4 a1 = make_float4(0.f, 0.f, 0.f, 0.f);
    const float* base = H + (size_t)lane * 4;
    int j = rs;
    for (; j + 1 < re; j += 2) {
        int s0 = __ldg(&g_srce[j]), s1 = __ldg(&g_srce[j + 1]);
        float4 v0 = *(const float4*)(base + (size_t)s0 * 128);
        float4 v1 = *(const float4*)(base + (size_t)s1 * 128);
        a0.x += v0.x; a0.y += v0.y; a0.z += v0.z; a0.w += v0.w;
        a1.x += v1.x; a1.y += v1.y; a1.z += v1.z; a1.w += v1.w;
    }
    if (j < re) {
        int s0 = __ldg(&g_srce[j]);
        float4 v0 = *(const float4*)(base + (size_t)s0 * 128);
        a0.x += v0.x; a0.y += v0.y; a0.z += v0.z; a0.w += v0.w;
    }
    a0.x += a1.x; a0.y += a1.y; a0.z += a1.z; a0.w += a1.w;
    *(float4*)(g_AGG + (size_t)w * 128 + lane * 4) = a0;
}

// ---------------- fp16 mma GEMM, cp.async double-buffered ----------------
// SMEM (floats): Asb0 [0,4608) Asb1 [4608,9216), then B halves region:
//   Bs0 at float-offset 9216 (2304 words), Bs1 at 11520. GSMEM = 13824*4.
#define GSMEM (13824 * 4)                            // 55296 B
#define FSMEM ((13824 + 128 * 132) * 4)              // 122880 B (+ fp32 X tile)

// MODE 0: plain A (K=128), bias+relu epilogue.
// MODE 1: stitched K=288 from A|AGG|TAIL, deg-scale after chunk 3, RELU.
// MODE 2: same as MODE 1 but NO relu (final layer).
template <int MODE>
__device__ __forceinline__ void stage_chunk(const float* __restrict__ A,
                                            const uint16_t* __restrict__ Bimg,
                                            float* AsBuf, uint32_t* BsBuf,
                                            int c, int block_row, int n, int tid) {
    const int k0 = c * 32;
    const float* srcbase;
    int stride, off;
    if (MODE == 0)      { srcbase = A;      stride = 128; off = k0; }
    else if (k0 < 128)  { srcbase = A;      stride = 128; off = k0; }
    else if (k0 < 256)  { srcbase = g_AGG;  stride = 128; off = k0 - 128; }
    else                { srcbase = g_TAIL; stride = 32;  off = 0; }
    #pragma unroll
    for (int l = 0; l < 4; l++) {
        int i = tid + l * 256;                 // 1024 = 128 rows x 8 float4
        int r = i >> 3, kq = (i & 7) << 2;
        int grow = block_row + r;
        uint32_t dst = (uint32_t)__cvta_generic_to_shared(AsBuf + r * 36 + kq);
        cpa16(dst, srcbase + (size_t)grow * stride + off + kq, grow < n ? 16 : 0);
    }
    // B chunk: 4608 halves = 9216 B = 576 x 16B
    const float4* bsrc = (const float4*)(Bimg + (size_t)c * 4608);
    #pragma unroll
    for (int l = 0; l < 3; l++) {
        int i = tid + l * 256;
        if (i < 576) {
            uint32_t dst = (uint32_t)__cvta_generic_to_shared((float4*)BsBuf + i);
            cpa16(dst, bsrc + i, 16);
        }
    }
}
__device__ __forceinline__ void stage_b_only(const uint16_t* __restrict__ Bimg,
                                             uint32_t* BsBuf, int c, int tid) {
    const float4* bsrc = (const float4*)(Bimg + (size_t)c * 4608);
    #pragma unroll
    for (int l = 0; l < 3; l++) {
        int i = tid + l * 256;
        if (i < 576) {
            uint32_t dst = (uint32_t)__cvta_generic_to_shared((float4*)BsBuf + i);
            cpa16(dst, bsrc + i, 16);
        }
    }
}

// One 32-k chunk: 2 x m16n8k16 steps. A read fp32 from SMEM (convert at load);
// B read directly as packed half2 words (word j = {B[2j][n], B[2j+1][n]}).
__device__ __forceinline__ void mma_chunk(float acc[4][4][4], const float* Asrc,
                                          int astride, int akoff, const uint32_t* Bs,
                                          int wr, int wc, int g, int tg) {
    #pragma unroll
    for (int ks = 0; ks < 2; ks++) {
        const int kb = akoff + ks * 16;
        uint32_t bfr[4][2];
        #pragma unroll
        for (int u = 0; u < 4; u++) {
            const int nn = wc + u * 8 + g;
            bfr[u][0] = Bs[nn * 18 + ks * 8 + tg];       // k = 2tg, 2tg+1
            bfr[u][1] = Bs[nn * 18 + ks * 8 + tg + 4];   // k = 2tg+8, 2tg+9
        }
        #pragma unroll
        for (int t = 0; t < 4; t++) {
            const int r0 = wr + t * 16 + g, r1 = r0 + 8;
            float2 x0 = *(const float2*)&Asrc[r0 * astride + kb + 2 * tg];
            float2 x1 = *(const float2*)&Asrc[r1 * astride + kb + 2 * tg];
            float2 x2 = *(const float2*)&Asrc[r0 * astride + kb + 2 * tg + 8];
            float2 x3 = *(const float2*)&Asrc[r1 * astride + kb + 2 * tg + 8];
            uint32_t a0 = f2h2(x0), a1 = f2h2(x1), a2 = f2h2(x2), a3 = f2h2(x3);
            #pragma unroll
            for (int u = 0; u < 4; u++)
                mma_f16(acc[t][u], a0, a1, a2, a3, bfr[u][0], bfr[u][1]);
        }
    }
}

// deg*(H·Wi) == (deg⊙H)·Wi  (row scaling commutes with right-multiplication)
__device__ __forceinline__ void scale_acc_deg(float acc[4][4][4], int block_row,
                                              int wr, int g, int n) {
    #pragma unroll
    for (int t = 0; t < 4; t++) {
        const int r0 = block_row + wr + t * 16 + g, r1 = r0 + 8;
        const float d0 = (r0 < n) ? g_DEG[r0] : 0.f;
        const float d1 = (r1 < n) ? g_DEG[r1] : 0.f;
        #pragma unroll
        for (int u = 0; u < 4; u++) {
            acc[t][u][0] *= d0; acc[t][u][1] *= d0;
            acc[t][u][2] *= d1; acc[t][u][3] *= d1;
        }
    }
}

template <int MODE>
__global__ __launch_bounds__(256, 2)
void gemm_mma_kernel(const float* __restrict__ A, const uint16_t* __restrict__ Bimg,
                     const float* __restrict__ bias, float* __restrict__ Cout, int n) {
    extern __shared__ __align__(16) float sm[];
    float* Asb[2] = { sm, sm + 4608 };
    uint32_t* Bsb[2] = { (uint32_t*)(sm + 9216), (uint32_t*)(sm + 11520) };
    const int tid = threadIdx.x, lane = tid & 31, wid = tid >> 5;
    const int g = lane >> 2, tg = lane & 3;
    const int wr = (wid & 1) * 64, wc = (wid >> 1) * 32;
    const int block_row = blockIdx.x * 128;
    const int CHUNKS = (MODE == 0) ? 4 : 9;

    float acc[4][4][4];
    #pragma unroll
    for (int t = 0; t < 4; t++)
        #pragma unroll
        for (int u = 0; u < 4; u++)
            #pragma unroll
            for (int v = 0; v < 4; v++) acc[t][u][v] = 0.f;

    stage_chunk<MODE>(A, Bimg, Asb[0], Bsb[0], 0, block_row, n, tid);
    CP_COMMIT();

    for (int c = 0; c < CHUNKS; c++) {
        const int cur = c & 1;
        if (c + 1 < CHUNKS)
            stage_chunk<MODE>(A, Bimg, Asb[(c + 1) & 1], Bsb[(c + 1) & 1],
                              c + 1, block_row, n, tid);
        CP_COMMIT();
        CP_WAIT1();
        __syncthreads();
        mma_chunk(acc, Asb[cur], 36, 0, Bsb[cur], wr, wc, g, tg);
        if (MODE != 0 && c == 3)             // end of H*Wi chunks -> apply deg
            scale_acc_deg(acc, block_row, wr, g, n);
        __syncthreads();
    }
    // ---- epilogue ----
    #pragma unroll
    for (int t = 0; t < 4; t++) {
        const int r0 = block_row + wr + t * 16 + g, r1 = r0 + 8;
        #pragma unroll
        for (int u = 0; u < 4; u++) {
            const int col = wc + u * 8 + tg * 2;
            float2 v0 = make_float2(acc[t][u][0], acc[t][u][1]);
            float2 v1 = make_float2(acc[t][u][2], acc[t][u][3]);
            if (MODE == 0) {
                float2 b2 = *(const float2*)(bias + col);
                v0.x = fmaxf(v0.x + b2.x, 0.f); v0.y = fmaxf(v0.y + b2.y, 0.f);
                v1.x = fmaxf(v1.x + b2.x, 0.f); v1.y = fmaxf(v1.y + b2.y, 0.f);
            } else if (MODE == 1) {
                v0.x = fmaxf(v0.x, 0.f); v0.y = fmaxf(v0.y, 0.f);
                v1.x = fmaxf(v1.x, 0.f); v1.y = fmaxf(v1.y, 0.f);
            }
            // MODE 2: raw accumulator (final layer, no relu)
            if (r0 < n) *(float2*)(Cout + (size_t)r0 * 128 + col) = v0;
            if (r1 < n) *(float2*)(Cout + (size_t)r1 * 128 + col) = v1;
        }
    }
}

// ---------------- FUSED: postGEMM layer1 + preGEMM layer2 ----
__global__ __launch_bounds__(256)
void gemm_fused_kernel(const float* __restrict__ Hin,
                       const uint16_t* __restrict__ Bimg1, const uint16_t* __restrict__ Bimg2,
                       const float* __restrict__ bias2, float* __restrict__ Hout, int n) {
    extern __shared__ __align__(16) float sm[];
    float* Asb[2] = { sm, sm + 4608 };
    uint32_t* Bsb[2] = { (uint32_t*)(sm + 9216), (uint32_t*)(sm + 11520) };
    float* Xt = sm + 13824;                 // 128 x 132 fp32 X tile
    const int tid = threadIdx.x, lane = tid & 31, wid = tid >> 5;
    const int g = lane >> 2, tg = lane & 3;
    const int wr = (wid & 1) * 64, wc = (wid >> 1) * 32;
    const int block_row = blockIdx.x * 128;

    float acc[4][4][4];
    #pragma unroll
    for (int t = 0; t < 4; t++)
        #pragma unroll
        for (int u = 0; u < 4; u++)
            #pragma unroll
            for (int v = 0; v < 4; v++) acc[t][u][v] = 0.f;

    // ================= GEMM 1 (stitched K=288) =================
    stage_chunk<1>(Hin, Bimg1, Asb[0], Bsb[0], 0, block_row, n, tid);
    CP_COMMIT();
    for (int c = 0; c < 9; c++) {
        const int cur = c & 1;
        if (c + 1 < 9)
            stage_chunk<1>(Hin, Bimg1, Asb[(c + 1) & 1], Bsb[(c + 1) & 1],
                           c + 1, block_row, n, tid);
        CP_COMMIT();
        CP_WAIT1();
        __syncthreads();
        mma_chunk(acc, Asb[cur], 36, 0, Bsb[cur], wr, wc, g, tg);
        if (c == 3)
            scale_acc_deg(acc, block_row, wr, g, n);
        __syncthreads();
    }
    // prefetch GEMM2's first B chunk while writing the X tile
    stage_b_only(Bimg2, Bsb[0], 0, tid);
    CP_COMMIT();
    // epilogue1 -> X tile (relu)
    #pragma unroll
    for (int t = 0; t < 4; t++) {
        const int r0 = wr + t * 16 + g, r1 = r0 + 8;
        #pragma unroll
        for (int u = 0; u < 4; u++) {
            const int col = wc + u * 8 + tg * 2;
            float2 v0 = make_float2(fmaxf(acc[t][u][0], 0.f), fmaxf(acc[t][u][1], 0.f));
            float2 v1 = make_float2(fmaxf(acc[t][u][2], 0.f), fmaxf(acc[t][u][3], 0.f));
            *(float2*)&Xt[r0 * 132 + col] = v0;
            *(float2*)&Xt[r1 * 132 + col] = v1;
        }
    }
    // ================= GEMM 2 (on X tile) =================
    #pragma unroll
    for (int t = 0; t < 4; t++)
        #pragma unroll
        for (int u = 0; u < 4; u++)
            #pragma unroll
            for (int v = 0; v < 4; v++) acc[t][u][v] = 0.f;
    __syncthreads();                        // X tile visible to all warps
    for (int c = 0; c < 4; c++) {
        const int cur = c & 1;
        if (c + 1 < 4)
            stage_b_only(Bimg2, Bsb[(c + 1) & 1], c + 1, tid);
        CP_COMMIT();
        CP_WAIT1();
        __syncthreads();
        mma_chunk(acc, Xt, 132, c * 32, Bsb[cur], wr, wc, g, tg);
        __syncthreads();
    }
    // epilogue2: relu(acc + bias2) -> g_H
    #pragma unroll
    for (int t = 0; t < 4; t++) {
        const int r0 = block_row + wr + t * 16 + g, r1 = r0 + 8;
        #pragma unroll
        for (int u = 0; u < 4; u++) {
            const int col = wc + u * 8 + tg * 2;
            float2 b2 = *(const float2*)(bias2 + col);
            float2 v0, v1;
            v0.x = fmaxf(acc[t][u][0] + b2.x, 0.f); v0.y = fmaxf(acc[t][u][1] + b2.y, 0.f);
            v1.x = fmaxf(acc[t][u][2] + b2.x, 0.f); v1.y = fmaxf(acc[t][u][3] + b2.y, 0.f);
            if (r0 < n) *(float2*)(Hout + (size_t)r0 * 128 + col) = v0;
            if (r1 < n) *(float2*)(Hout + (size_t)r1 * 128 + col) = v1;
        }
    }
}

// ---------------- link-prediction head ----------------
__global__ __launch_bounds__(256)
void head_kernel(const float* __restrict__ X, const void* __restrict__ eli,
                 const float* __restrict__ lpW, const float* __restrict__ lpb,
                 float* __restrict__ out, int Q) {
    int w = (blockIdx.x * blockDim.x + threadIdx.x) >> 5;
    int lane = threadIdx.x & 31;
    if (w >= Q) return;
    float2 wa[4], wb[4];
    #pragma unroll
    for (int i = 0; i < 4; i++) {
        wa[i] = *(const float2*)(lpW + (size_t)(4 * lane + i) * 2);
        wb[i] = *(const float2*)(lpW + (size_t)(128 + 4 * lane + i) * 2);
    }
    int i0 = 0, i1 = 0;
    if (lane == 0) {
        if (g_q64) {
            i0 = (int)((const long long*)eli)[w];
            i1 = (int)((const long long*)eli)[(size_t)Q + w];
        } else {
            i0 = ((const int*)eli)[w];
            i1 = ((const int*)eli)[(size_t)Q + w];
        }
    }
    i0 = __shfl_sync(0xffffffffu, i0, 0);
    i1 = __shfl_sync(0xffffffffu, i1, 0);
    float4 a = *(const float4*)(X + (size_t)i0 * 128 + lane * 4);
    float4 b = *(const float4*)(X + (size_t)i1 * 128 + lane * 4);
    float p0 = a.x * wa[0].x + a.y * wa[1].x + a.z * wa[2].x + a.w * wa[3].x
             + b.x * wb[0].x + b.y * wb[1].x + b.z * wb[2].x + b.w * wb[3].x;
    float p1 = a.x * wa[0].y + a.y * wa[1].y + a.z * wa[2].y + a.w * wa[3].y
             + b.x * wb[0].y + b.y * wb[1].y + b.z * wb[2].y + b.w * wb[3].y;
    #pragma unroll
    for (int off = 16; off; off >>= 1) {
        p0 += __shfl_down_sync(0xffffffffu, p0, off);
        p1 += __shfl_down_sync(0xffffffffu, p1, off);
    }
    if (lane == 0) {
        out[(size_t)2 * w + 0] = p0 + lpb[0];
        out[(size_t)2 * w + 1] = p1 + lpb[1];
    }
}

// ---------------- launch ----------------
extern "C" void kernel_launch(void* const* d_in, const int* in_sizes, int n_in,
                              void* d_out, int out_size) {
    const float* node_feature = (const float*)d_in[0];
    const void*  edge_index   = d_in[1];
    const float* edge_feature = (const float*)d_in[2];
    const void*  eli          = d_in[3];
    const float* c1_pre_W = (const float*)d_in[4];
    const float* c1_pre_b = (const float*)d_in[5];
    const float* c1_msg_W = (const float*)d_in[6];
    const float* c1_msg_b = (const float*)d_in[7];
    const float* c2_pre_W = (const float*)d_in[8];
    const float* c2_pre_b = (const float*)d_in[9];
    const float* c2_msg_W = (const float*)d_in[10];
    const float* c2_msg_b = (const float*)d_in[11];
    const float* lp_W     = (const float*)d_in[12];
    const float* lp_b     = (const float*)d_in[13];
    float* out = (float*)d_out;

    const int N = in_sizes[0] / D;
    const int E = in_sizes[1] / 2;
    const int Q = in_sizes[3] / 2;

    float *H, *X;
    uint16_t *Bpre, *Bpost;
    cudaGetSymbolAddress((void**)&H,  g_H);
    cudaGetSymbolAddress((void**)&X,  g_X);
    cudaGetSymbolAddress((void**)&Bpre, g_Bpre16);
    cudaGetSymbolAddress((void**)&Bpost, g_Bpost16);
    uint16_t* Bpre1  = Bpre;
    uint16_t* Bpre2  = Bpre + 4 * 4608;
    uint16_t* Bpost1 = Bpost;
    uint16_t* Bpost2 = Bpost + 9 * 4608;

    static int init_done = 0;
    static cudaStream_t s2;
    static cudaEvent_t evF, evFill, evEagg;
    if (!init_done) {
        cudaFuncSetAttribute(gemm_mma_kernel<0>, cudaFuncAttributeMaxDynamicSharedMemorySize, GSMEM);
        cudaFuncSetAttribute(gemm_mma_kernel<2>, cudaFuncAttributeMaxDynamicSharedMemorySize, GSMEM);
        cudaFuncSetAttribute(gemm_fused_kernel, cudaFuncAttributeMaxDynamicSharedMemorySize, FSMEM);
        cudaStreamCreateWithFlags(&s2, cudaStreamNonBlocking);
        cudaEventCreateWithFlags(&evF, cudaEventDisableTiming);
        cudaEventCreateWithFlags(&evFill, cudaEventDisableTiming);
        cudaEventCreateWithFlags(&evEagg, cudaEventDisableTiming);
        init_done = 1;
    }

    const int gemm_blocks  = (N + 127) / 128;
    const int warp8_blocks = (N + 7) / 8;
    const int edge_blocks  = (E + 255) / 256;
    const int nb = (N + 255) / 256;

    // root: zero counters + dtype detect
    detect_zero_kernel<<<nb, 256>>>((const int*)edge_index, (const int*)eli, N);

    // ---- fork: CSR build on side stream ----
    cudaEventRecord(evF, 0);
    cudaStreamWaitEvent(s2, evF, 0);
    hist_kernel<<<edge_blocks, 256, 0, s2>>>(edge_index, E);
    scan1_kernel<<<nb, 256, 0, s2>>>(N);
    scan2_kernel<<<1, 512, 0, s2>>>(nb);
    scan3_kernel<<<(N + 256) / 256, 256, 0, s2>>>(N, E);
    fill_kernel<<<edge_blocks, 256, 0, s2>>>(edge_index, E);
    cudaEventRecord(evFill, s2);
    eagg_tail_kernel<<<warp8_blocks, 256, 0, s2>>>(edge_feature, N);   // concurrent with gather
    cudaEventRecord(evEagg, s2);

    // ---- main stream: weight prep + layer-1 pre-GEMM ----
    prep_all_kernel<<<(106496 + 255) / 256, 256>>>(c1_pre_W, c2_pre_W,
                                                   c1_msg_W, c1_msg_b,
                                                   c2_msg_W, c2_msg_b,
                                                   Bpre1, Bpre2, Bpost1, Bpost2);
    gemm_mma_kernel<0><<<gemm_blocks, 256, GSMEM>>>(node_feature, Bpre1, c1_pre_b, H, N);

    // ---- join 1: CSR arrays ready -> gather (concurrent with eagg on s2) ----
    cudaStreamWaitEvent(0, evFill, 0);
    gather_agg_kernel<<<warp8_blocks, 256>>>(H, N);

    // ---- join 2: TAIL ready -> fused postGEMM1 + preGEMM2 (H overwritten) ----
    cudaStreamWaitEvent(0, evEagg, 0);
    gemm_fused_kernel<<<gemm_blocks, 256, FSMEM>>>(H, Bpost1, Bpre2, c2_pre_b, H, N);

    // layer 2 rest (MODE 2: stitched, NO relu — final output)
    gather_agg_kernel<<<warp8_blocks, 256>>>(H, N);
    gemm_mma_kernel<2><<<gemm_blocks, 256, GSMEM>>>(H, Bpost2, nullptr, X, N);

    head_kernel<<<(Q + 7) / 8, 256>>>(X, eli, lp_W, lp_b, out, Q);
}

// round 15
// speedup vs baseline: 1.4946x; 1.0636x over previous
#include <cuda_runtime.h>
#include <cuda_fp16.h>
#include <cstdint>

#define NN 50000
#define EE 500000
#define D  128

// ---------------- device scratch (no allocation allowed) ----------------
__device__ __align__(16) uint16_t g_H16[(size_t)NN * D];  // fp16 pre-conv output
__device__ float g_X[(size_t)NN * D];            // final conv output (head input)
__device__ float g_AGG[(size_t)NN * D];          // gathered neighbor sum (fp32)
__device__ float g_TAIL[(size_t)NN * 32];        // [eagg(16) | deg | 0...]
__device__ float g_DEG[NN];
__device__ int   g_cnt[NN], g_cur[NN];
__device__ int   g_off[NN + 1];
__device__ int   g_srce[EE], g_eid[EE];
__device__ int   g_bsum[512], g_bsum2[512];
__device__ int   g_e64, g_q64;
// fp16 B images, fragment-paired half2 layout, 36-half (18-word) padded rows.
__device__ uint16_t g_Bpre16[2][4 * 4608];    // K=128 -> 4 chunks
__device__ uint16_t g_Bpost16[2][9 * 4608];   // K=288 -> 9 chunks

// ---------------- helpers ----------------
__device__ __forceinline__ uint32_t f2h2(float2 v) {
    uint32_t o;
    asm("cvt.rn.f16x2.f32 %0, %1, %2;" : "=r"(o) : "f"(v.y), "f"(v.x));
    return o;
}
__device__ __forceinline__ void mma_f16(float* c, uint32_t a0, uint32_t a1,
                                        uint32_t a2, uint32_t a3,
                                        uint32_t b0, uint32_t b1) {
    asm volatile(
        "mma.sync.aligned.m16n8k16.row.col.f32.f16.f16.f32 "
        "{%0,%1,%2,%3}, {%4,%5,%6,%7}, {%8,%9}, {%0,%1,%2,%3};"
        : "+f"(c[0]), "+f"(c[1]), "+f"(c[2]), "+f"(c[3])
        : "r"(a0), "r"(a1), "r"(a2), "r"(a3), "r"(b0), "r"(b1));
}
__device__ __forceinline__ void cpa16(uint32_t dst, const void* src, int sz) {
    asm volatile("cp.async.cg.shared.global [%0], [%1], 16, %2;"
                 :: "r"(dst), "l"(src), "r"(sz) : "memory");
}
#define CP_COMMIT() asm volatile("cp.async.commit_group;" ::: "memory")
#define CP_WAIT1()  asm volatile("cp.async.wait_group 1;" ::: "memory")

// ---------------- fused detect (warp-parallel) + zero ----------------
__global__ void detect_zero_kernel(const int* __restrict__ ei, const int* __restrict__ eli, int n) {
    int i = blockIdx.x * blockDim.x + threadIdx.x;
    if (i < n) { g_cnt[i] = 0; g_cur[i] = 0; }
    if (blockIdx.x == 0 && threadIdx.x < 32) {
        int lane = threadIdx.x;
        int a = 0, b = 0;
        #pragma unroll
        for (int j = 0; j < 4; j++) {
            a |= ei[2 * (lane * 4 + j) + 1];
            b |= eli[2 * (lane * 4 + j) + 1];
        }
        unsigned ba = __ballot_sync(0xffffffffu, a != 0);
        unsigned bb = __ballot_sync(0xffffffffu, b != 0);
        if (lane == 0) {
            g_e64 = (ba == 0) ? 1 : 0;
            g_q64 = (bb == 0) ? 1 : 0;
        }
    }
}

// ---------------- fused B-image prep (fp16) ----------------
__device__ __forceinline__ void prep_one(const float* W, const float* bias,
                                         uint16_t* img, int K_eff, int idx) {
    int n = idx & 127;
    int k = idx >> 7;
    float v = 0.f;
    if (k < K_eff) v = W[(size_t)k * 128 + n];
    else if (k == K_eff && bias != nullptr) v = bias[n];
    __half h = __float2half_rn(v);
    img[(size_t)(k >> 5) * 4608 + n * 36 + (k & 31)] = *(uint16_t*)&h;
}
__global__ void prep_all_kernel(const float* W1, const float* W2,
                                const float* W3, const float* b3,
                                const float* W4, const float* b4,
                                uint16_t* img1, uint16_t* img2,
                                uint16_t* img3, uint16_t* img4) {
    int idx = blockIdx.x * blockDim.x + threadIdx.x;
    if (idx < 16384)       prep_one(W1, nullptr, img1, 128, idx);
    else if (idx < 32768)  prep_one(W2, nullptr, img2, 128, idx - 16384);
    else if (idx < 69632)  prep_one(W3, b3, img3, 272, idx - 32768);
    else if (idx < 106496) prep_one(W4, b4, img4, 272, idx - 69632);
}

// ---------------- CSR build ----------------
__global__ void hist_kernel(const void* __restrict__ ei, int E) {
    int e = blockIdx.x * blockDim.x + threadIdx.x;
    if (e >= E) return;
    int d = g_e64 ? (int)((const long long*)ei)[(size_t)E + e] : ((const int*)ei)[(size_t)E + e];
    atomicAdd(&g_cnt[d], 1);
}
__global__ void scan1_kernel(int n) {
    __shared__ int s[256];
    int idx = blockIdx.x * 256 + threadIdx.x;
    int v = (idx < n) ? g_cnt[idx] : 0;
    s[threadIdx.x] = v; __syncthreads();
    #pragma unroll
    for (int o = 1; o < 256; o <<= 1) {
        int t = (threadIdx.x >= o) ? s[threadIdx.x - o] : 0;
        __syncthreads(); s[threadIdx.x] += t; __syncthreads();
    }
    if (idx < n) g_off[idx] = s[threadIdx.x] - v;
    if (threadIdx.x == 255) g_bsum[blockIdx.x] = s[255];
}
// Warp-shuffle scan of up to 512 block sums (512 threads, 1 block).
__global__ void scan2_kernel(int nb) {
    __shared__ int wsum[16];
    int tid = threadIdx.x;            // 0..511
    int lane = tid & 31, wid = tid >> 5;
    int v = (tid < nb) ? g_bsum[tid] : 0;
    int x = v;
    #pragma unroll
    for (int o = 1; o < 32; o <<= 1) {
        int t = __shfl_up_sync(0xffffffffu, x, o);
        if (lane >= o) x += t;
    }
    if (lane == 31) wsum[wid] = x;
    __syncthreads();
    if (wid == 0) {
        int s = (lane < 16) ? wsum[lane] : 0;
        #pragma unroll
        for (int o = 1; o < 16; o <<= 1) {
            int t = __shfl_up_sync(0xffffffffu, s, o);
            if (lane >= o) s += t;
        }
        if (lane < 16) wsum[lane] = s;
    }
    __syncthreads();
    int base = (wid > 0) ? wsum[wid - 1] : 0;
    g_bsum2[tid] = base + x - v;      // exclusive
}
__global__ void scan3_kernel(int n, int E) {
    int idx = blockIdx.x * blockDim.x + threadIdx.x;
    if (idx < n) {
        g_off[idx] += g_bsum2[idx >> 8];
        g_DEG[idx] = (float)g_cnt[idx];
    }
    if (idx == n) g_off[n] = E;
}
__global__ void fill_kernel(const void* __restrict__ ei, int E) {
    int e = blockIdx.x * blockDim.x + threadIdx.x;
    if (e >= E) return;
    int s, d;
    if (g_e64) {
        s = (int)((const long long*)ei)[e];
        d = (int)((const long long*)ei)[(size_t)E + e];
    } else {
        s = ((const int*)ei)[e];
        d = ((const int*)ei)[(size_t)E + e];
    }
    int pos = g_off[d] + atomicAdd(&g_cur[d], 1);
    g_srce[pos] = s;
    g_eid[pos]  = e;
}
// eagg + TAIL pack: TAIL[w][0..15]=eagg, [16]=deg, [17..31]=0
__global__ __launch_bounds__(256)
void eagg_tail_kernel(const float* __restrict__ ef, int n) {
    int w = (blockIdx.x * blockDim.x + threadIdx.x) >> 5;
    int lane = threadIdx.x & 31;
    if (w >= n) return;
    int rs = g_off[w], re = g_off[w + 1];
    float acc = 0.f;
    if (lane < 16) {
        for (int j = rs; j < re; j++) {
            int e = __ldg(&g_eid[j]);
            acc += __ldg(ef + (size_t)e * 16 + lane);
        }
    } else if (lane == 16) {
        acc = g_DEG[w];
    }
    g_TAIL[(size_t)w * 32 + lane] = acc;
}

// ---------------- aggregation gather (atomic-free, fp16 H reads) ----------
__global__ __launch_bounds__(256)
void gather_agg_kernel(int n) {
    int w = (blockIdx.x * blockDim.x + threadIdx.x) >> 5;
    int lane = threadIdx.x & 31;
    if (w >= n) return;
    int rs = g_off[w], re = g_off[w + 1];
    float4 a0 = make_float4(0.f, 0.f, 0.f, 0.f);
    float4 a1 = make_float4(0.f, 0.f, 0.f, 0.f);
    const uint16_t* base = g_H16 + lane * 4;   // 4 halves per lane
    int j = rs;
    for (; j + 1 < re; j += 2) {
        int s0 = __ldg(&g_srce[j]), s1 = __ldg(&g_srce[j + 1]);
        uint2 u0 = *(const uint2*)(base + (size_t)s0 * 128);
        uint2 u1 = *(const uint2*)(base + (size_t)s1 * 128);
        float2 p0 = __half22float2(*(__half2*)&u0.x);
        float2 p1 = __half22float2(*(__half2*)&u0.y);
        float2 q0 = __half22float2(*(__half2*)&u1.x);
        float2 q1 = __half22float2(*(__half2*)&u1.y);
        a0.x += p0.x; a0.y += p0.y; a0.z += p1.x; a0.w += p1.y;
        a1.x += q0.x; a1.y += q0.y; a1.z += q1.x; a1.w += q1.y;
    }
    if (j < re) {
        int s0 = __ldg(&g_srce[j]);
        uint2 u0 = *(const uint2*)(base + (size_t)s0 * 128);
        float2 p0 = __half22float2(*(__half2*)&u0.x);
        float2 p1 = __half22float2(*(__half2*)&u0.y);
        a0.x += p0.x; a0.y += p0.y; a0.z += p1.x; a0.w += p1.y;
    }
    a0.x += a1.x; a0.y += a1.y; a0.z += a1.z; a0.w += a1.w;
    *(float4*)(g_AGG + (size_t)w * 128 + lane * 4) = a0;
}

// ---------------- fp16 mma GEMM, cp.async double-buffered ----------------
// SMEM (floats): Asb0 [0,4608) Asb1 [4608,9216), B: Bs0 at 9216, Bs1 at 11520.
#define GSMEM (13824 * 4)                            // 55296 B
#define FSMEM ((13824 + 128 * 132) * 4)              // 122880 B (+ fp32 X tile)

// MODE 0: plain fp32 A (K=128), bias+relu, fp16 output (H16).
// MODE 1: stitched K=288 from H16|AGG|TAIL, deg-scale after chunk 3, RELU.
// MODE 2: same as MODE 1 but NO relu, fp32 output (X, final layer).
// Stitched chunks 0-3 stage fp16 H16 tiles (smem rows: 80 B = 20 words,
// conflict-free: (g*20+tg) mod 32 is a permutation); chunks 4+ stage fp32.
template <int MODE>
__device__ __forceinline__ void stage_chunk(const float* __restrict__ A,
                                            const uint16_t* __restrict__ Bimg,
                                            float* AsBuf, uint32_t* BsBuf,
                                            int c, int block_row, int n, int tid) {
    const int k0 = c * 32;
    if (MODE != 0 && k0 < 128) {
        // fp16 tile: 128 rows x 64 B data in 80 B smem rows (512 x 16B)
        #pragma unroll
        for (int l = 0; l < 2; l++) {
            int i = tid + l * 256;
            int r = i >> 2, j = i & 3;
            int grow = block_row + r;
            uint32_t dst = (uint32_t)__cvta_generic_to_shared((char*)AsBuf + r * 80 + j * 16);
            cpa16(dst, (const char*)g_H16 + (size_t)grow * 256 + k0 * 2 + j * 16,
                  grow < n ? 16 : 0);
        }
    } else {
        const float* srcbase;
        int stride, off;
        if (MODE == 0)     { srcbase = A;      stride = 128; off = k0; }
        else if (k0 < 256) { srcbase = g_AGG;  stride = 128; off = k0 - 128; }
        else               { srcbase = g_TAIL; stride = 32;  off = 0; }
        #pragma unroll
        for (int l = 0; l < 4; l++) {
            int i = tid + l * 256;                 // 1024 = 128 rows x 8 float4
            int r = i >> 3, kq = (i & 7) << 2;
            int grow = block_row + r;
            uint32_t dst = (uint32_t)__cvta_generic_to_shared(AsBuf + r * 36 + kq);
            cpa16(dst, srcbase + (size_t)grow * stride + off + kq, grow < n ? 16 : 0);
        }
    }
    // B chunk: 4608 halves = 9216 B = 576 x 16B
    const float4* bsrc = (const float4*)(Bimg + (size_t)c * 4608);
    #pragma unroll
    for (int l = 0; l < 3; l++) {
        int i = tid + l * 256;
        if (i < 576) {
            uint32_t dst = (uint32_t)__cvta_generic_to_shared((float4*)BsBuf + i);
            cpa16(dst, bsrc + i, 16);
        }
    }
}
__device__ __forceinline__ void stage_b_only(const uint16_t* __restrict__ Bimg,
                                             uint32_t* BsBuf, int c, int tid) {
    const float4* bsrc = (const float4*)(Bimg + (size_t)c * 4608);
    #pragma unroll
    for (int l = 0; l < 3; l++) {
        int i = tid + l * 256;
        if (i < 576) {
            uint32_t dst = (uint32_t)__cvta_generic_to_shared((float4*)BsBuf + i);
            cpa16(dst, bsrc + i, 16);
        }
    }
}

// fp32-A chunk: convert at fragment load.
__device__ __forceinline__ void mma_chunk(float acc[4][4][4], const float* Asrc,
                                          int astride, int akoff, const uint32_t* Bs,
                                          int wr, int wc, int g, int tg) {
    #pragma unroll
    for (int ks = 0; ks < 2; ks++) {
        const int kb = akoff + ks * 16;
        uint32_t bfr[4][2];
        #pragma unroll
        for (int u = 0; u < 4; u++) {
            const int nn = wc + u * 8 + g;
            bfr[u][0] = Bs[nn * 18 + ks * 8 + tg];
            bfr[u][1] = Bs[nn * 18 + ks * 8 + tg + 4];
        }
        #pragma unroll
        for (int t = 0; t < 4; t++) {
            const int r0 = wr + t * 16 + g, r1 = r0 + 8;
            float2 x0 = *(const float2*)&Asrc[r0 * astride + kb + 2 * tg];
            float2 x1 = *(const float2*)&Asrc[r1 * astride + kb + 2 * tg];
            float2 x2 = *(const float2*)&Asrc[r0 * astride + kb + 2 * tg + 8];
            float2 x3 = *(const float2*)&Asrc[r1 * astride + kb + 2 * tg + 8];
            uint32_t a0 = f2h2(x0), a1 = f2h2(x1), a2 = f2h2(x2), a3 = f2h2(x3);
            #pragma unroll
            for (int u = 0; u < 4; u++)
                mma_f16(acc[t][u], a0, a1, a2, a3, bfr[u][0], bfr[u][1]);
        }
    }
}
// fp16-A chunk: direct packed loads (rows of 20 words).
__device__ __forceinline__ void mma_chunk_h(float acc[4][4][4], const uint32_t* As,
                                            const uint32_t* Bs,
                                            int wr, int wc, int g, int tg) {
    #pragma unroll
    for (int ks = 0; ks < 2; ks++) {
        uint32_t bfr[4][2];
        #pragma unroll
        for (int u = 0; u < 4; u++) {
            const int nn = wc + u * 8 + g;
            bfr[u][0] = Bs[nn * 18 + ks * 8 + tg];
            bfr[u][1] = Bs[nn * 18 + ks * 8 + tg + 4];
        }
        #pragma unroll
        for (int t = 0; t < 4; t++) {
            const int r0 = wr + t * 16 + g, r1 = r0 + 8;
            uint32_t a0 = As[r0 * 20 + ks * 8 + tg];
            uint32_t a1 = As[r1 * 20 + ks * 8 + tg];
            uint32_t a2 = As[r0 * 20 + ks * 8 + tg + 4];
            uint32_t a3 = As[r1 * 20 + ks * 8 + tg + 4];
            #pragma unroll
            for (int u = 0; u < 4; u++)
                mma_f16(acc[t][u], a0, a1, a2, a3, bfr[u][0], bfr[u][1]);
        }
    }
}

// deg*(H·Wi) == (deg⊙H)·Wi
__device__ __forceinline__ void scale_acc_deg(float acc[4][4][4], int block_row,
                                              int wr, int g, int n) {
    #pragma unroll
    for (int t = 0; t < 4; t++) {
        const int r0 = block_row + wr + t * 16 + g, r1 = r0 + 8;
        const float d0 = (r0 < n) ? g_DEG[r0] : 0.f;
        const float d1 = (r1 < n) ? g_DEG[r1] : 0.f;
        #pragma unroll
        for (int u = 0; u < 4; u++) {
            acc[t][u][0] *= d0; acc[t][u][1] *= d0;
            acc[t][u][2] *= d1; acc[t][u][3] *= d1;
        }
    }
}

template <int MODE>
__global__ __launch_bounds__(256, 2)
void gemm_mma_kernel(const float* __restrict__ A, const uint16_t* __restrict__ Bimg,
                     const float* __restrict__ bias, void* __restrict__ Cout, int n) {
    extern __shared__ __align__(16) float sm[];
    float* Asb[2] = { sm, sm + 4608 };
    uint32_t* Bsb[2] = { (uint32_t*)(sm + 9216), (uint32_t*)(sm + 11520) };
    const int tid = threadIdx.x, lane = tid & 31, wid = tid >> 5;
    const int g = lane >> 2, tg = lane & 3;
    const int wr = (wid & 1) * 64, wc = (wid >> 1) * 32;
    const int block_row = blockIdx.x * 128;
    const int CHUNKS = (MODE == 0) ? 4 : 9;

    float acc[4][4][4];
    #pragma unroll
    for (int t = 0; t < 4; t++)
        #pragma unroll
        for (int u = 0; u < 4; u++)
            #pragma unroll
            for (int v = 0; v < 4; v++) acc[t][u][v] = 0.f;

    stage_chunk<MODE>(A, Bimg, Asb[0], Bsb[0], 0, block_row, n, tid);
    CP_COMMIT();

    for (int c = 0; c < CHUNKS; c++) {
        const int cur = c & 1;
        if (c + 1 < CHUNKS)
            stage_chunk<MODE>(A, Bimg, Asb[(c + 1) & 1], Bsb[(c + 1) & 1],
                              c + 1, block_row, n, tid);
        CP_COMMIT();
        CP_WAIT1();
        __syncthreads();
        if (MODE != 0 && c < 4)
            mma_chunk_h(acc, (const uint32_t*)Asb[cur], Bsb[cur], wr, wc, g, tg);
        else
            mma_chunk(acc, Asb[cur], 36, 0, Bsb[cur], wr, wc, g, tg);
        if (MODE != 0 && c == 3)
            scale_acc_deg(acc, block_row, wr, g, n);
        __syncthreads();
    }
    // ---- epilogue ----
    #pragma unroll
    for (int t = 0; t < 4; t++) {
        const int r0 = block_row + wr + t * 16 + g, r1 = r0 + 8;
        #pragma unroll
        for (int u = 0; u < 4; u++) {
            const int col = wc + u * 8 + tg * 2;
            float2 v0 = make_float2(acc[t][u][0], acc[t][u][1]);
            float2 v1 = make_float2(acc[t][u][2], acc[t][u][3]);
            if (MODE == 0) {
                float2 b2 = *(const float2*)(bias + col);
                v0.x = fmaxf(v0.x + b2.x, 0.f); v0.y = fmaxf(v0.y + b2.y, 0.f);
                v1.x = fmaxf(v1.x + b2.x, 0.f); v1.y = fmaxf(v1.y + b2.y, 0.f);
                // fp16 H output
                if (r0 < n) *(uint32_t*)((char*)Cout + (size_t)r0 * 256 + col * 2) = f2h2(v0);
                if (r1 < n) *(uint32_t*)((char*)Cout + (size_t)r1 * 256 + col * 2) = f2h2(v1);
            } else {
                if (MODE == 1) {
                    v0.x = fmaxf(v0.x, 0.f); v0.y = fmaxf(v0.y, 0.f);
                    v1.x = fmaxf(v1.x, 0.f); v1.y = fmaxf(v1.y, 0.f);
                }
                if (r0 < n) *(float2*)((float*)Cout + (size_t)r0 * 128 + col) = v0;
                if (r1 < n) *(float2*)((float*)Cout + (size_t)r1 * 128 + col) = v1;
            }
        }
    }
}

// ---------------- FUSED: postGEMM layer1 + preGEMM layer2 ----
// GEMM1: stitched K=288 (H16|AGG|TAIL, deg-scale after chunk 3) -> relu -> X tile.
// GEMM2: X tile (fp32 SMEM) x Bpre2, +bias2, relu -> g_H16 (layer-2 H).
__global__ __launch_bounds__(256)
void gemm_fused_kernel(const uint16_t* __restrict__ Bimg1, const uint16_t* __restrict__ Bimg2,
                       const float* __restrict__ bias2, int n) {
    extern __shared__ __align__(16) float sm[];
    float* Asb[2] = { sm, sm + 4608 };
    uint32_t* Bsb[2] = { (uint32_t*)(sm + 9216), (uint32_t*)(sm + 11520) };
    float* Xt = sm + 13824;                 // 128 x 132 fp32 X tile
    const int tid = threadIdx.x, lane = tid & 31, wid = tid >> 5;
    const int g = lane >> 2, tg = lane & 3;
    const int wr = (wid & 1) * 64, wc = (wid >> 1) * 32;
    const int block_row = blockIdx.x * 128;

    float acc[4][4][4];
    #pragma unroll
    for (int t = 0; t < 4; t++)
        #pragma unroll
        for (int u = 0; u < 4; u++)
            #pragma unroll
            for (int v = 0; v < 4; v++) acc[t][u][v] = 0.f;

    // ================= GEMM 1 (stitched K=288) =================
    stage_chunk<1>(nullptr, Bimg1, Asb[0], Bsb[0], 0, block_row, n, tid);
    CP_COMMIT();
    for (int c = 0; c < 9; c++) {
        const int cur = c & 1;
        if (c + 1 < 9)
            stage_chunk<1>(nullptr, Bimg1, Asb[(c + 1) & 1], Bsb[(c + 1) & 1],
                           c + 1, block_row, n, tid);
        CP_COMMIT();
        CP_WAIT1();
        __syncthreads();
        if (c < 4)
            mma_chunk_h(acc, (const uint32_t*)Asb[cur], Bsb[cur], wr, wc, g, tg);
        else
            mma_chunk(acc, Asb[cur], 36, 0, Bsb[cur], wr, wc, g, tg);
        if (c == 3)
            scale_acc_deg(acc, block_row, wr, g, n);
        __syncthreads();
    }
    // prefetch GEMM2's first B chunk while writing the X tile
    stage_b_only(Bimg2, Bsb[0], 0, tid);
    CP_COMMIT();
    // epilogue1 -> X tile (relu)
    #pragma unroll
    for (int t = 0; t < 4; t++) {
        const int r0 = wr + t * 16 + g, r1 = r0 + 8;
        #pragma unroll
        for (int u = 0; u < 4; u++) {
            const int col = wc + u * 8 + tg * 2;
            float2 v0 = make_float2(fmaxf(acc[t][u][0], 0.f), fmaxf(acc[t][u][1], 0.f));
            float2 v1 = make_float2(fmaxf(acc[t][u][2], 0.f), fmaxf(acc[t][u][3], 0.f));
            *(float2*)&Xt[r0 * 132 + col] = v0;
            *(float2*)&Xt[r1 * 132 + col] = v1;
        }
    }
    // ================= GEMM 2 (on X tile) =================
    #pragma unroll
    for (int t = 0; t < 4; t++)
        #pragma unroll
        for (int u = 0; u < 4; u++)
            #pragma unroll
            for (int v = 0; v < 4; v++) acc[t][u][v] = 0.f;
    __syncthreads();                        // X tile visible to all warps
    for (int c = 0; c < 4; c++) {
        const int cur = c & 1;
        if (c + 1 < 4)
            stage_b_only(Bimg2, Bsb[(c + 1) & 1], c + 1, tid);
        CP_COMMIT();
        CP_WAIT1();
        __syncthreads();
        mma_chunk(acc, Xt, 132, c * 32, Bsb[cur], wr, wc, g, tg);
        __syncthreads();
    }
    // epilogue2: relu(acc + bias2) -> g_H16 (fp16)
    #pragma unroll
    for (int t = 0; t < 4; t++) {
        const int r0 = block_row + wr + t * 16 + g, r1 = r0 + 8;
        #pragma unroll
        for (int u = 0; u < 4; u++) {
            const int col = wc + u * 8 + tg * 2;
            float2 b2 = *(const float2*)(bias2 + col);
            float2 v0, v1;
            v0.x = fmaxf(acc[t][u][0] + b2.x, 0.f); v0.y = fmaxf(acc[t][u][1] + b2.y, 0.f);
            v1.x = fmaxf(acc[t][u][2] + b2.x, 0.f); v1.y = fmaxf(acc[t][u][3] + b2.y, 0.f);
            if (r0 < n) *(uint32_t*)((char*)g_H16 + (size_t)r0 * 256 + col * 2) = f2h2(v0);
            if (r1 < n) *(uint32_t*)((char*)g_H16 + (size_t)r1 * 256 + col * 2) = f2h2(v1);
        }
    }
}

// ---------------- link-prediction head ----------------
__global__ __launch_bounds__(256)
void head_kernel(const float* __restrict__ X, const void* __restrict__ eli,
                 const float* __restrict__ lpW, const float* __restrict__ lpb,
                 float* __restrict__ out, int Q) {
    int w = (blockIdx.x * blockDim.x + threadIdx.x) >> 5;
    int lane = threadIdx.x & 31;
    if (w >= Q) return;
    float2 wa[4], wb[4];
    #pragma unroll
    for (int i = 0; i < 4; i++) {
        wa[i] = *(const float2*)(lpW + (size_t)(4 * lane + i) * 2);
        wb[i] = *(const float2*)(lpW + (size_t)(128 + 4 * lane + i) * 2);
    }
    int i0 = 0, i1 = 0;
    if (lane == 0) {
        if (g_q64) {
            i0 = (int)((const long long*)eli)[w];
            i1 = (int)((const long long*)eli)[(size_t)Q + w];
        } else {
            i0 = ((const int*)eli)[w];
            i1 = ((const int*)eli)[(size_t)Q + w];
        }
    }
    i0 = __shfl_sync(0xffffffffu, i0, 0);
    i1 = __shfl_sync(0xffffffffu, i1, 0);
    float4 a = *(const float4*)(X + (size_t)i0 * 128 + lane * 4);
    float4 b = *(const float4*)(X + (size_t)i1 * 128 + lane * 4);
    float p0 = a.x * wa[0].x + a.y * wa[1].x + a.z * wa[2].x + a.w * wa[3].x
             + b.x * wb[0].x + b.y * wb[1].x + b.z * wb[2].x + b.w * wb[3].x;
    float p1 = a.x * wa[0].y + a.y * wa[1].y + a.z * wa[2].y + a.w * wa[3].y
             + b.x * wb[0].y + b.y * wb[1].y + b.z * wb[2].y + b.w * wb[3].y;
    #pragma unroll
    for (int off = 16; off; off >>= 1) {
        p0 += __shfl_down_sync(0xffffffffu, p0, off);
        p1 += __shfl_down_sync(0xffffffffu, p1, off);
    }
    if (lane == 0) {
        out[(size_t)2 * w + 0] = p0 + lpb[0];
        out[(size_t)2 * w + 1] = p1 + lpb[1];
    }
}

// ---------------- launch ----------------
extern "C" void kernel_launch(void* const* d_in, const int* in_sizes, int n_in,
                              void* d_out, int out_size) {
    const float* node_feature = (const float*)d_in[0];
    const void*  edge_index   = d_in[1];
    const float* edge_feature = (const float*)d_in[2];
    const void*  eli          = d_in[3];
    const float* c1_pre_W = (const float*)d_in[4];
    const float* c1_pre_b = (const float*)d_in[5];
    const float* c1_msg_W = (const float*)d_in[6];
    const float* c1_msg_b = (const float*)d_in[7];
    const float* c2_pre_W = (const float*)d_in[8];
    const float* c2_pre_b = (const float*)d_in[9];
    const float* c2_msg_W = (const float*)d_in[10];
    const float* c2_msg_b = (const float*)d_in[11];
    const float* lp_W     = (const float*)d_in[12];
    const float* lp_b     = (const float*)d_in[13];
    float* out = (float*)d_out;

    const int N = in_sizes[0] / D;
    const int E = in_sizes[1] / 2;
    const int Q = in_sizes[3] / 2;

    float *X;
    uint16_t *H16, *Bpre, *Bpost;
    cudaGetSymbolAddress((void**)&H16, g_H16);
    cudaGetSymbolAddress((void**)&X,   g_X);
    cudaGetSymbolAddress((void**)&Bpre, g_Bpre16);
    cudaGetSymbolAddress((void**)&Bpost, g_Bpost16);
    uint16_t* Bpre1  = Bpre;
    uint16_t* Bpre2  = Bpre + 4 * 4608;
    uint16_t* Bpost1 = Bpost;
    uint16_t* Bpost2 = Bpost + 9 * 4608;

    static int init_done = 0;
    static cudaStream_t s2;
    static cudaEvent_t evF, evFill, evEagg;
    if (!init_done) {
        cudaFuncSetAttribute(gemm_mma_kernel<0>, cudaFuncAttributeMaxDynamicSharedMemorySize, GSMEM);
        cudaFuncSetAttribute(gemm_mma_kernel<2>, cudaFuncAttributeMaxDynamicSharedMemorySize, GSMEM);
        cudaFuncSetAttribute(gemm_fused_kernel, cudaFuncAttributeMaxDynamicSharedMemorySize, FSMEM);
        cudaStreamCreateWithFlags(&s2, cudaStreamNonBlocking);
        cudaEventCreateWithFlags(&evF, cudaEventDisableTiming);
        cudaEventCreateWithFlags(&evFill, cudaEventDisableTiming);
        cudaEventCreateWithFlags(&evEagg, cudaEventDisableTiming);
        init_done = 1;
    }

    const int gemm_blocks  = (N + 127) / 128;
    const int warp8_blocks = (N + 7) / 8;
    const int edge_blocks  = (E + 255) / 256;
    const int nb = (N + 255) / 256;

    // root: zero counters + dtype detect
    detect_zero_kernel<<<nb, 256>>>((const int*)edge_index, (const int*)eli, N);

    // ---- fork: CSR build on side stream ----
    cudaEventRecord(evF, 0);
    cudaStreamWaitEvent(s2, evF, 0);
    hist_kernel<<<edge_blocks, 256, 0, s2>>>(edge_index, E);
    scan1_kernel<<<nb, 256, 0, s2>>>(N);
    scan2_kernel<<<1, 512, 0, s2>>>(nb);
    scan3_kernel<<<(N + 256) / 256, 256, 0, s2>>>(N, E);
    fill_kernel<<<edge_blocks, 256, 0, s2>>>(edge_index, E);
    cudaEventRecord(evFill, s2);
    eagg_tail_kernel<<<warp8_blocks, 256, 0, s2>>>(edge_feature, N);   // concurrent with gather
    cudaEventRecord(evEagg, s2);

    // ---- main stream: weight prep + layer-1 pre-GEMM (H16 output) ----
    prep_all_kernel<<<(106496 + 255) / 256, 256>>>(c1_pre_W, c2_pre_W,
                                                   c1_msg_W, c1_msg_b,
                                                   c2_msg_W, c2_msg_b,
                                                   Bpre1, Bpre2, Bpost1, Bpost2);
    gemm_mma_kernel<0><<<gemm_blocks, 256, GSMEM>>>(node_feature, Bpre1, c1_pre_b, H16, N);

    // ---- join 1: CSR arrays ready -> gather (concurrent with eagg on s2) ----
    cudaStreamWaitEvent(0, evFill, 0);
    gather_agg_kernel<<<warp8_blocks, 256>>>(N);

    // ---- join 2: TAIL ready -> fused postGEMM1 + preGEMM2 (H16 overwritten) ----
    cudaStreamWaitEvent(0, evEagg, 0);
    gemm_fused_kernel<<<gemm_blocks, 256, FSMEM>>>(Bpost1, Bpre2, c2_pre_b, N);

    // layer 2 rest (MODE 2: stitched, NO relu — final output X fp32)
    gather_agg_kernel<<<warp8_blocks, 256>>>(N);
    gemm_mma_kernel<2><<<gemm_blocks, 256, GSMEM>>>(nullptr, Bpost2, nullptr, X, N);

    head_kernel<<<(Q + 7) / 8, 256>>>(X, eli, lp_W, lp_b, out, Q);
}

// round 16
// speedup vs baseline: 1.5780x; 1.0558x over previous
#include <cuda_runtime.h>
#include <cuda_fp16.h>
#include <cstdint>

#define NN 50000
#define EE 500000
#define D  128

// ---------------- device scratch (no allocation allowed) ----------------
__device__ __align__(16) uint16_t g_H16[(size_t)NN * D];  // fp16 pre-conv output
__device__ float g_X[(size_t)NN * D];            // final conv output (head input)
__device__ float g_AGG[(size_t)NN * D];          // gathered neighbor sum (fp32)
__device__ float g_TAIL[(size_t)NN * 32];        // [eagg(16) | deg | 0...]
__device__ float g_DEG[NN];
__device__ int   g_cnt[NN], g_cur[NN];
__device__ int   g_off[NN + 1];
__device__ int   g_srce[EE], g_eid[EE];
__device__ int   g_bsum[512], g_bsum2[512];
__device__ int   g_e64, g_q64;
// fp16 B images, fragment-paired half2 layout, 36-half (18-word) padded rows.
__device__ uint16_t g_Bpre16[2][4 * 4608];    // K=128 -> 4 chunks
__device__ uint16_t g_Bpost16[2][9 * 4608];   // K=288 -> 9 chunks

// ---------------- helpers ----------------
__device__ __forceinline__ uint32_t f2h2(float2 v) {
    uint32_t o;
    asm("cvt.rn.f16x2.f32 %0, %1, %2;" : "=r"(o) : "f"(v.y), "f"(v.x));
    return o;
}
__device__ __forceinline__ void mma_f16(float* c, uint32_t a0, uint32_t a1,
                                        uint32_t a2, uint32_t a3,
                                        uint32_t b0, uint32_t b1) {
    asm volatile(
        "mma.sync.aligned.m16n8k16.row.col.f32.f16.f16.f32 "
        "{%0,%1,%2,%3}, {%4,%5,%6,%7}, {%8,%9}, {%0,%1,%2,%3};"
        : "+f"(c[0]), "+f"(c[1]), "+f"(c[2]), "+f"(c[3])
        : "r"(a0), "r"(a1), "r"(a2), "r"(a3), "r"(b0), "r"(b1));
}
__device__ __forceinline__ void cpa16(uint32_t dst, const void* src, int sz) {
    asm volatile("cp.async.cg.shared.global [%0], [%1], 16, %2;"
                 :: "r"(dst), "l"(src), "r"(sz) : "memory");
}
#define CP_COMMIT() asm volatile("cp.async.commit_group;" ::: "memory")
#define CP_WAIT1()  asm volatile("cp.async.wait_group 1;" ::: "memory")

// ---------------- fused detect (warp-parallel) + zero ----------------
__global__ void detect_zero_kernel(const int* __restrict__ ei, const int* __restrict__ eli, int n) {
    int i = blockIdx.x * blockDim.x + threadIdx.x;
    if (i < n) { g_cnt[i] = 0; g_cur[i] = 0; }
    if (blockIdx.x == 0 && threadIdx.x < 32) {
        int lane = threadIdx.x;
        int a = 0, b = 0;
        #pragma unroll
        for (int j = 0; j < 4; j++) {
            a |= ei[2 * (lane * 4 + j) + 1];
            b |= eli[2 * (lane * 4 + j) + 1];
        }
        unsigned ba = __ballot_sync(0xffffffffu, a != 0);
        unsigned bb = __ballot_sync(0xffffffffu, b != 0);
        if (lane == 0) {
            g_e64 = (ba == 0) ? 1 : 0;
            g_q64 = (bb == 0) ? 1 : 0;
        }
    }
}

// ---------------- fused B-image prep (fp16) ----------------
__device__ __forceinline__ void prep_one(const float* W, const float* bias,
                                         uint16_t* img, int K_eff, int idx) {
    int n = idx & 127;
    int k = idx >> 7;
    float v = 0.f;
    if (k < K_eff) v = W[(size_t)k * 128 + n];
    else if (k == K_eff && bias != nullptr) v = bias[n];
    __half h = __float2half_rn(v);
    img[(size_t)(k >> 5) * 4608 + n * 36 + (k & 31)] = *(uint16_t*)&h;
}
__global__ void prep_all_kernel(const float* W1, const float* W2,
                                const float* W3, const float* b3,
                                const float* W4, const float* b4,
                                uint16_t* img1, uint16_t* img2,
                                uint16_t* img3, uint16_t* img4) {
    int idx = blockIdx.x * blockDim.x + threadIdx.x;
    if (idx < 16384)       prep_one(W1, nullptr, img1, 128, idx);
    else if (idx < 32768)  prep_one(W2, nullptr, img2, 128, idx - 16384);
    else if (idx < 69632)  prep_one(W3, b3, img3, 272, idx - 32768);
    else if (idx < 106496) prep_one(W4, b4, img4, 272, idx - 69632);
}

// ---------------- CSR build ----------------
__global__ void hist_kernel(const void* __restrict__ ei, int E) {
    int e = blockIdx.x * blockDim.x + threadIdx.x;
    if (e >= E) return;
    int d = g_e64 ? (int)((const long long*)ei)[(size_t)E + e] : ((const int*)ei)[(size_t)E + e];
    atomicAdd(&g_cnt[d], 1);
}
__global__ void scan1_kernel(int n) {
    __shared__ int s[256];
    int idx = blockIdx.x * 256 + threadIdx.x;
    int v = (idx < n) ? g_cnt[idx] : 0;
    s[threadIdx.x] = v; __syncthreads();
    #pragma unroll
    for (int o = 1; o < 256; o <<= 1) {
        int t = (threadIdx.x >= o) ? s[threadIdx.x - o] : 0;
        __syncthreads(); s[threadIdx.x] += t; __syncthreads();
    }
    if (idx < n) g_off[idx] = s[threadIdx.x] - v;
    if (threadIdx.x == 255) g_bsum[blockIdx.x] = s[255];
}
// Warp-shuffle scan of up to 512 block sums (512 threads, 1 block).
__global__ void scan2_kernel(int nb) {
    __shared__ int wsum[16];
    int tid = threadIdx.x;            // 0..511
    int lane = tid & 31, wid = tid >> 5;
    int v = (tid < nb) ? g_bsum[tid] : 0;
    int x = v;
    #pragma unroll
    for (int o = 1; o < 32; o <<= 1) {
        int t = __shfl_up_sync(0xffffffffu, x, o);
        if (lane >= o) x += t;
    }
    if (lane == 31) wsum[wid] = x;
    __syncthreads();
    if (wid == 0) {
        int s = (lane < 16) ? wsum[lane] : 0;
        #pragma unroll
        for (int o = 1; o < 16; o <<= 1) {
            int t = __shfl_up_sync(0xffffffffu, s, o);
            if (lane >= o) s += t;
        }
        if (lane < 16) wsum[lane] = s;
    }
    __syncthreads();
    int base = (wid > 0) ? wsum[wid - 1] : 0;
    g_bsum2[tid] = base + x - v;      // exclusive
}
__global__ void scan3_kernel(int n, int E) {
    int idx = blockIdx.x * blockDim.x + threadIdx.x;
    if (idx < n) {
        g_off[idx] += g_bsum2[idx >> 8];
        g_DEG[idx] = (float)g_cnt[idx];
    }
    if (idx == n) g_off[n] = E;
}
__global__ void fill_kernel(const void* __restrict__ ei, int E) {
    int e = blockIdx.x * blockDim.x + threadIdx.x;
    if (e >= E) return;
    int s, d;
    if (g_e64) {
        s = (int)((const long long*)ei)[e];
        d = (int)((const long long*)ei)[(size_t)E + e];
    } else {
        s = ((const int*)ei)[e];
        d = ((const int*)ei)[(size_t)E + e];
    }
    int pos = g_off[d] + atomicAdd(&g_cur[d], 1);
    g_srce[pos] = s;
    g_eid[pos]  = e;
}
// eagg + TAIL pack: TAIL[w][0..15]=eagg, [16]=deg, [17..31]=0
__global__ __launch_bounds__(256)
void eagg_tail_kernel(const float* __restrict__ ef, int n) {
    int w = (blockIdx.x * blockDim.x + threadIdx.x) >> 5;
    int lane = threadIdx.x & 31;
    if (w >= n) return;
    int rs = g_off[w], re = g_off[w + 1];
    float acc = 0.f;
    if (lane < 16) {
        for (int j = rs; j < re; j++) {
            int e = __ldg(&g_eid[j]);
            acc += __ldg(ef + (size_t)e * 16 + lane);
        }
    } else if (lane == 16) {
        acc = g_DEG[w];
    }
    g_TAIL[(size_t)w * 32 + lane] = acc;
}

// ---------------- aggregation gather (atomic-free, fp16 H reads) ----------
__global__ __launch_bounds__(256)
void gather_agg_kernel(int n) {
    int w = (blockIdx.x * blockDim.x + threadIdx.x) >> 5;
    int lane = threadIdx.x & 31;
    if (w >= n) return;
    int rs = g_off[w], re = g_off[w + 1];
    float4 a0 = make_float4(0.f, 0.f, 0.f, 0.f);
    float4 a1 = make_float4(0.f, 0.f, 0.f, 0.f);
    const uint16_t* base = g_H16 + lane * 4;   // 4 halves per lane
    int j = rs;
    for (; j + 1 < re; j += 2) {
        int s0 = __ldg(&g_srce[j]), s1 = __ldg(&g_srce[j + 1]);
        uint2 u0 = *(const uint2*)(base + (size_t)s0 * 128);
        uint2 u1 = *(const uint2*)(base + (size_t)s1 * 128);
        float2 p0 = __half22float2(*(__half2*)&u0.x);
        float2 p1 = __half22float2(*(__half2*)&u0.y);
        float2 q0 = __half22float2(*(__half2*)&u1.x);
        float2 q1 = __half22float2(*(__half2*)&u1.y);
        a0.x += p0.x; a0.y += p0.y; a0.z += p1.x; a0.w += p1.y;
        a1.x += q0.x; a1.y += q0.y; a1.z += q1.x; a1.w += q1.y;
    }
    if (j < re) {
        int s0 = __ldg(&g_srce[j]);
        uint2 u0 = *(const uint2*)(base + (size_t)s0 * 128);
        float2 p0 = __half22float2(*(__half2*)&u0.x);
        float2 p1 = __half22float2(*(__half2*)&u0.y);
        a0.x += p0.x; a0.y += p0.y; a0.z += p1.x; a0.w += p1.y;
    }
    a0.x += a1.x; a0.y += a1.y; a0.z += a1.z; a0.w += a1.w;
    *(float4*)(g_AGG + (size_t)w * 128 + lane * 4) = a0;
}

// ---------------- fp16 mma GEMM, cp.async double-buffered ----------------
// SMEM (floats): Asb0 [0,4608) Asb1 [4608,9216), B: Bs0 at 9216, Bs1 at 11520.
#define GSMEM (13824 * 4)                            // 55296 B
#define FSMEM ((13824 + 4 * 2560) * 4)               // 96256 B (+ fp16 X tile)

// MODE 0: plain fp32 A (K=128), bias+relu, fp16 output (H16).
// MODE 1: stitched K=288 from H16|AGG|TAIL, deg-scale after chunk 3, RELU.
// MODE 2: same as MODE 1 but NO relu, fp32 output (X, final layer).
// Stitched chunks 0-3 stage fp16 H16 tiles (smem rows: 80 B = 20 words,
// conflict-free: (g*20+tg) mod 32 is a permutation); chunks 4+ stage fp32.
template <int MODE>
__device__ __forceinline__ void stage_chunk(const float* __restrict__ A,
                                            const uint16_t* __restrict__ Bimg,
                                            float* AsBuf, uint32_t* BsBuf,
                                            int c, int block_row, int n, int tid) {
    const int k0 = c * 32;
    if (MODE != 0 && k0 < 128) {
        // fp16 tile: 128 rows x 64 B data in 80 B smem rows (512 x 16B)
        #pragma unroll
        for (int l = 0; l < 2; l++) {
            int i = tid + l * 256;
            int r = i >> 2, j = i & 3;
            int grow = block_row + r;
            uint32_t dst = (uint32_t)__cvta_generic_to_shared((char*)AsBuf + r * 80 + j * 16);
            cpa16(dst, (const char*)g_H16 + (size_t)grow * 256 + k0 * 2 + j * 16,
                  grow < n ? 16 : 0);
        }
    } else {
        const float* srcbase;
        int stride, off;
        if (MODE == 0)     { srcbase = A;      stride = 128; off = k0; }
        else if (k0 < 256) { srcbase = g_AGG;  stride = 128; off = k0 - 128; }
        else               { srcbase = g_TAIL; stride = 32;  off = 0; }
        #pragma unroll
        for (int l = 0; l < 4; l++) {
            int i = tid + l * 256;                 // 1024 = 128 rows x 8 float4
            int r = i >> 3, kq = (i & 7) << 2;
            int grow = block_row + r;
            uint32_t dst = (uint32_t)__cvta_generic_to_shared(AsBuf + r * 36 + kq);
            cpa16(dst, srcbase + (size_t)grow * stride + off + kq, grow < n ? 16 : 0);
        }
    }
    // B chunk: 4608 halves = 9216 B = 576 x 16B
    const float4* bsrc = (const float4*)(Bimg + (size_t)c * 4608);
    #pragma unroll
    for (int l = 0; l < 3; l++) {
        int i = tid + l * 256;
        if (i < 576) {
            uint32_t dst = (uint32_t)__cvta_generic_to_shared((float4*)BsBuf + i);
            cpa16(dst, bsrc + i, 16);
        }
    }
}
__device__ __forceinline__ void stage_b_only(const uint16_t* __restrict__ Bimg,
                                             uint32_t* BsBuf, int c, int tid) {
    const float4* bsrc = (const float4*)(Bimg + (size_t)c * 4608);
    #pragma unroll
    for (int l = 0; l < 3; l++) {
        int i = tid + l * 256;
        if (i < 576) {
            uint32_t dst = (uint32_t)__cvta_generic_to_shared((float4*)BsBuf + i);
            cpa16(dst, bsrc + i, 16);
        }
    }
}

// fp32-A chunk: convert at fragment load.
__device__ __forceinline__ void mma_chunk(float acc[4][4][4], const float* Asrc,
                                          int astride, int akoff, const uint32_t* Bs,
                                          int wr, int wc, int g, int tg) {
    #pragma unroll
    for (int ks = 0; ks < 2; ks++) {
        const int kb = akoff + ks * 16;
        uint32_t bfr[4][2];
        #pragma unroll
        for (int u = 0; u < 4; u++) {
            const int nn = wc + u * 8 + g;
            bfr[u][0] = Bs[nn * 18 + ks * 8 + tg];
            bfr[u][1] = Bs[nn * 18 + ks * 8 + tg + 4];
        }
        #pragma unroll
        for (int t = 0; t < 4; t++) {
            const int r0 = wr + t * 16 + g, r1 = r0 + 8;
            float2 x0 = *(const float2*)&Asrc[r0 * astride + kb + 2 * tg];
            float2 x1 = *(const float2*)&Asrc[r1 * astride + kb + 2 * tg];
            float2 x2 = *(const float2*)&Asrc[r0 * astride + kb + 2 * tg + 8];
            float2 x3 = *(const float2*)&Asrc[r1 * astride + kb + 2 * tg + 8];
            uint32_t a0 = f2h2(x0), a1 = f2h2(x1), a2 = f2h2(x2), a3 = f2h2(x3);
            #pragma unroll
            for (int u = 0; u < 4; u++)
                mma_f16(acc[t][u], a0, a1, a2, a3, bfr[u][0], bfr[u][1]);
        }
    }
}
// fp16-A chunk: direct packed loads (rows of 20 words; word j = k pair (2j,2j+1)).
__device__ __forceinline__ void mma_chunk_h(float acc[4][4][4], const uint32_t* As,
                                            const uint32_t* Bs,
                                            int wr, int wc, int g, int tg) {
    #pragma unroll
    for (int ks = 0; ks < 2; ks++) {
        uint32_t bfr[4][2];
        #pragma unroll
        for (int u = 0; u < 4; u++) {
            const int nn = wc + u * 8 + g;
            bfr[u][0] = Bs[nn * 18 + ks * 8 + tg];
            bfr[u][1] = Bs[nn * 18 + ks * 8 + tg + 4];
        }
        #pragma unroll
        for (int t = 0; t < 4; t++) {
            const int r0 = wr + t * 16 + g, r1 = r0 + 8;
            uint32_t a0 = As[r0 * 20 + ks * 8 + tg];
            uint32_t a1 = As[r1 * 20 + ks * 8 + tg];
            uint32_t a2 = As[r0 * 20 + ks * 8 + tg + 4];
            uint32_t a3 = As[r1 * 20 + ks * 8 + tg + 4];
            #pragma unroll
            for (int u = 0; u < 4; u++)
                mma_f16(acc[t][u], a0, a1, a2, a3, bfr[u][0], bfr[u][1]);
        }
    }
}

// deg*(H·Wi) == (deg⊙H)·Wi
__device__ __forceinline__ void scale_acc_deg(float acc[4][4][4], int block_row,
                                              int wr, int g, int n) {
    #pragma unroll
    for (int t = 0; t < 4; t++) {
        const int r0 = block_row + wr + t * 16 + g, r1 = r0 + 8;
        const float d0 = (r0 < n) ? g_DEG[r0] : 0.f;
        const float d1 = (r1 < n) ? g_DEG[r1] : 0.f;
        #pragma unroll
        for (int u = 0; u < 4; u++) {
            acc[t][u][0] *= d0; acc[t][u][1] *= d0;
            acc[t][u][2] *= d1; acc[t][u][3] *= d1;
        }
    }
}

template <int MODE>
__global__ __launch_bounds__(256, 2)
void gemm_mma_kernel(const float* __restrict__ A, const uint16_t* __restrict__ Bimg,
                     const float* __restrict__ bias, void* __restrict__ Cout, int n) {
    extern __shared__ __align__(16) float sm[];
    float* Asb[2] = { sm, sm + 4608 };
    uint32_t* Bsb[2] = { (uint32_t*)(sm + 9216), (uint32_t*)(sm + 11520) };
    const int tid = threadIdx.x, lane = tid & 31, wid = tid >> 5;
    const int g = lane >> 2, tg = lane & 3;
    const int wr = (wid & 1) * 64, wc = (wid >> 1) * 32;
    const int block_row = blockIdx.x * 128;
    const int CHUNKS = (MODE == 0) ? 4 : 9;

    float acc[4][4][4];
    #pragma unroll
    for (int t = 0; t < 4; t++)
        #pragma unroll
        for (int u = 0; u < 4; u++)
            #pragma unroll
            for (int v = 0; v < 4; v++) acc[t][u][v] = 0.f;

    stage_chunk<MODE>(A, Bimg, Asb[0], Bsb[0], 0, block_row, n, tid);
    CP_COMMIT();

    for (int c = 0; c < CHUNKS; c++) {
        const int cur = c & 1;
        if (c + 1 < CHUNKS)
            stage_chunk<MODE>(A, Bimg, Asb[(c + 1) & 1], Bsb[(c + 1) & 1],
                              c + 1, block_row, n, tid);
        CP_COMMIT();
        CP_WAIT1();
        __syncthreads();
        if (MODE != 0 && c < 4)
            mma_chunk_h(acc, (const uint32_t*)Asb[cur], Bsb[cur], wr, wc, g, tg);
        else
            mma_chunk(acc, Asb[cur], 36, 0, Bsb[cur], wr, wc, g, tg);
        if (MODE != 0 && c == 3)
            scale_acc_deg(acc, block_row, wr, g, n);
        __syncthreads();
    }
    // ---- epilogue ----
    #pragma unroll
    for (int t = 0; t < 4; t++) {
        const int r0 = block_row + wr + t * 16 + g, r1 = r0 + 8;
        #pragma unroll
        for (int u = 0; u < 4; u++) {
            const int col = wc + u * 8 + tg * 2;
            float2 v0 = make_float2(acc[t][u][0], acc[t][u][1]);
            float2 v1 = make_float2(acc[t][u][2], acc[t][u][3]);
            if (MODE == 0) {
                float2 b2 = *(const float2*)(bias + col);
                v0.x = fmaxf(v0.x + b2.x, 0.f); v0.y = fmaxf(v0.y + b2.y, 0.f);
                v1.x = fmaxf(v1.x + b2.x, 0.f); v1.y = fmaxf(v1.y + b2.y, 0.f);
                if (r0 < n) *(uint32_t*)((char*)Cout + (size_t)r0 * 256 + col * 2) = f2h2(v0);
                if (r1 < n) *(uint32_t*)((char*)Cout + (size_t)r1 * 256 + col * 2) = f2h2(v1);
            } else {
                if (MODE == 1) {
                    v0.x = fmaxf(v0.x, 0.f); v0.y = fmaxf(v0.y, 0.f);
                    v1.x = fmaxf(v1.x, 0.f); v1.y = fmaxf(v1.y, 0.f);
                }
                if (r0 < n) *(float2*)((float*)Cout + (size_t)r0 * 128 + col) = v0;
                if (r1 < n) *(float2*)((float*)Cout + (size_t)r1 * 128 + col) = v1;
            }
        }
    }
}

// ---------------- FUSED: postGEMM layer1 + preGEMM layer2 ----
// GEMM1: stitched K=288 (H16|AGG|TAIL, deg-scale after chunk 3) -> relu ->
//        fp16 X tile in staged-chunk layout (4 chunks x 128 rows x 20 words).
// GEMM2: X tile (fp16 SMEM) x Bpre2, +bias2, relu -> g_H16 (layer-2 H).
__global__ __launch_bounds__(256, 2)
void gemm_fused_kernel(const uint16_t* __restrict__ Bimg1, const uint16_t* __restrict__ Bimg2,
                       const float* __restrict__ bias2, int n) {
    extern __shared__ __align__(16) float sm[];
    float* Asb[2] = { sm, sm + 4608 };
    uint32_t* Bsb[2] = { (uint32_t*)(sm + 9216), (uint32_t*)(sm + 11520) };
    uint32_t* Xt = (uint32_t*)(sm + 13824);   // 4 chunks x 2560 words (fp16 pairs)
    const int tid = threadIdx.x, lane = tid & 31, wid = tid >> 5;
    const int g = lane >> 2, tg = lane & 3;
    const int wr = (wid & 1) * 64, wc = (wid >> 1) * 32;
    const int block_row = blockIdx.x * 128;

    float acc[4][4][4];
    #pragma unroll
    for (int t = 0; t < 4; t++)
        #pragma unroll
        for (int u = 0; u < 4; u++)
            #pragma unroll
            for (int v = 0; v < 4; v++) acc[t][u][v] = 0.f;

    // ================= GEMM 1 (stitched K=288) =================
    stage_chunk<1>(nullptr, Bimg1, Asb[0], Bsb[0], 0, block_row, n, tid);
    CP_COMMIT();
    for (int c = 0; c < 9; c++) {
        const int cur = c & 1;
        if (c + 1 < 9)
            stage_chunk<1>(nullptr, Bimg1, Asb[(c + 1) & 1], Bsb[(c + 1) & 1],
                           c + 1, block_row, n, tid);
        CP_COMMIT();
        CP_WAIT1();
        __syncthreads();
        if (c < 4)
            mma_chunk_h(acc, (const uint32_t*)Asb[cur], Bsb[cur], wr, wc, g, tg);
        else
            mma_chunk(acc, Asb[cur], 36, 0, Bsb[cur], wr, wc, g, tg);
        if (c == 3)
            scale_acc_deg(acc, block_row, wr, g, n);
        __syncthreads();
    }
    // prefetch GEMM2's first B chunk while writing the X tile
    stage_b_only(Bimg2, Bsb[0], 0, tid);
    CP_COMMIT();
    // epilogue1 -> fp16 X tile (relu); word (col&31)>>1 of chunk col>>5
    #pragma unroll
    for (int t = 0; t < 4; t++) {
        const int r0 = wr + t * 16 + g, r1 = r0 + 8;
        #pragma unroll
        for (int u = 0; u < 4; u++) {
            const int col = wc + u * 8 + tg * 2;
            const int base = (col >> 5) * 2560 + ((col & 31) >> 1);
            float2 v0 = make_float2(fmaxf(acc[t][u][0], 0.f), fmaxf(acc[t][u][1], 0.f));
            float2 v1 = make_float2(fmaxf(acc[t][u][2], 0.f), fmaxf(acc[t][u][3], 0.f));
            Xt[base + r0 * 20] = f2h2(v0);
            Xt[base + r1 * 20] = f2h2(v1);
        }
    }
    // ================= GEMM 2 (fp16 X tile) =================
    #pragma unroll
    for (int t = 0; t < 4; t++)
        #pragma unroll
        for (int u = 0; u < 4; u++)
            #pragma unroll
            for (int v = 0; v < 4; v++) acc[t][u][v] = 0.f;
    __syncthreads();                        // X tile visible to all warps
    for (int c = 0; c < 4; c++) {
        const int cur = c & 1;
        if (c + 1 < 4)
            stage_b_only(Bimg2, Bsb[(c + 1) & 1], c + 1, tid);
        CP_COMMIT();
        CP_WAIT1();
        __syncthreads();
        mma_chunk_h(acc, Xt + c * 2560, Bsb[cur], wr, wc, g, tg);
        __syncthreads();
    }
    // epilogue2: relu(acc + bias2) -> g_H16 (fp16)
    #pragma unroll
    for (int t = 0; t < 4; t++) {
        const int r0 = block_row + wr + t * 16 + g, r1 = r0 + 8;
        #pragma unroll
        for (int u = 0; u < 4; u++) {
            const int col = wc + u * 8 + tg * 2;
            float2 b2 = *(const float2*)(bias2 + col);
            float2 v0, v1;
            v0.x = fmaxf(acc[t][u][0] + b2.x, 0.f); v0.y = fmaxf(acc[t][u][1] + b2.y, 0.f);
            v1.x = fmaxf(acc[t][u][2] + b2.x, 0.f); v1.y = fmaxf(acc[t][u][3] + b2.y, 0.f);
            if (r0 < n) *(uint32_t*)((char*)g_H16 + (size_t)r0 * 256 + col * 2) = f2h2(v0);
            if (r1 < n) *(uint32_t*)((char*)g_H16 + (size_t)r1 * 256 + col * 2) = f2h2(v1);
        }
    }
}

// ---------------- link-prediction head ----------------
__global__ __launch_bounds__(256)
void head_kernel(const float* __restrict__ X, const void* __restrict__ eli,
                 const float* __restrict__ lpW, const float* __restrict__ lpb,
                 float* __restrict__ out, int Q) {
    int w = (blockIdx.x * blockDim.x + threadIdx.x) >> 5;
    int lane = threadIdx.x & 31;
    if (w >= Q) return;
    float2 wa[4], wb[4];
    #pragma unroll
    for (int i = 0; i < 4; i++) {
        wa[i] = *(const float2*)(lpW + (size_t)(4 * lane + i) * 2);
        wb[i] = *(const float2*)(lpW + (size_t)(128 + 4 * lane + i) * 2);
    }
    int i0 = 0, i1 = 0;
    if (lane == 0) {
        if (g_q64) {
            i0 = (int)((const long long*)eli)[w];
            i1 = (int)((const long long*)eli)[(size_t)Q + w];
        } else {
            i0 = ((const int*)eli)[w];
            i1 = ((const int*)eli)[(size_t)Q + w];
        }
    }
    i0 = __shfl_sync(0xffffffffu, i0, 0);
    i1 = __shfl_sync(0xffffffffu, i1, 0);
    float4 a = *(const float4*)(X + (size_t)i0 * 128 + lane * 4);
    float4 b = *(const float4*)(X + (size_t)i1 * 128 + lane * 4);
    float p0 = a.x * wa[0].x + a.y * wa[1].x + a.z * wa[2].x + a.w * wa[3].x
             + b.x * wb[0].x + b.y * wb[1].x + b.z * wb[2].x + b.w * wb[3].x;
    float p1 = a.x * wa[0].y + a.y * wa[1].y + a.z * wa[2].y + a.w * wa[3].y
             + b.x * wb[0].y + b.y * wb[1].y + b.z * wb[2].y + b.w * wb[3].y;
    #pragma unroll
    for (int off = 16; off; off >>= 1) {
        p0 += __shfl_down_sync(0xffffffffu, p0, off);
        p1 += __shfl_down_sync(0xffffffffu, p1, off);
    }
    if (lane == 0) {
        out[(size_t)2 * w + 0] = p0 + lpb[0];
        out[(size_t)2 * w + 1] = p1 + lpb[1];
    }
}

// ---------------- launch ----------------
extern "C" void kernel_launch(void* const* d_in, const int* in_sizes, int n_in,
                              void* d_out, int out_size) {
    const float* node_feature = (const float*)d_in[0];
    const void*  edge_index   = d_in[1];
    const float* edge_feature = (const float*)d_in[2];
    const void*  eli          = d_in[3];
    const float* c1_pre_W = (const float*)d_in[4];
    const float* c1_pre_b = (const float*)d_in[5];
    const float* c1_msg_W = (const float*)d_in[6];
    const float* c1_msg_b = (const float*)d_in[7];
    const float* c2_pre_W = (const float*)d_in[8];
    const float* c2_pre_b = (const float*)d_in[9];
    const float* c2_msg_W = (const float*)d_in[10];
    const float* c2_msg_b = (const float*)d_in[11];
    const float* lp_W     = (const float*)d_in[12];
    const float* lp_b     = (const float*)d_in[13];
    float* out = (float*)d_out;

    const int N = in_sizes[0] / D;
    const int E = in_sizes[1] / 2;
    const int Q = in_sizes[3] / 2;

    float *X;
    uint16_t *H16, *Bpre, *Bpost;
    cudaGetSymbolAddress((void**)&H16, g_H16);
    cudaGetSymbolAddress((void**)&X,   g_X);
    cudaGetSymbolAddress((void**)&Bpre, g_Bpre16);
    cudaGetSymbolAddress((void**)&Bpost, g_Bpost16);
    uint16_t* Bpre1  = Bpre;
    uint16_t* Bpre2  = Bpre + 4 * 4608;
    uint16_t* Bpost1 = Bpost;
    uint16_t* Bpost2 = Bpost + 9 * 4608;

    static int init_done = 0;
    static cudaStream_t s2;
    static cudaEvent_t evF, evFill, evEagg;
    if (!init_done) {
        cudaFuncSetAttribute(gemm_mma_kernel<0>, cudaFuncAttributeMaxDynamicSharedMemorySize, GSMEM);
        cudaFuncSetAttribute(gemm_mma_kernel<2>, cudaFuncAttributeMaxDynamicSharedMemorySize, GSMEM);
        cudaFuncSetAttribute(gemm_fused_kernel, cudaFuncAttributeMaxDynamicSharedMemorySize, FSMEM);
        cudaStreamCreateWithFlags(&s2, cudaStreamNonBlocking);
        cudaEventCreateWithFlags(&evF, cudaEventDisableTiming);
        cudaEventCreateWithFlags(&evFill, cudaEventDisableTiming);
        cudaEventCreateWithFlags(&evEagg, cudaEventDisableTiming);
        init_done = 1;
    }

    const int gemm_blocks  = (N + 127) / 128;
    const int warp8_blocks = (N + 7) / 8;
    const int edge_blocks  = (E + 255) / 256;
    const int nb = (N + 255) / 256;

    // root: zero counters + dtype detect
    detect_zero_kernel<<<nb, 256>>>((const int*)edge_index, (const int*)eli, N);

    // ---- fork: CSR build on side stream ----
    cudaEventRecord(evF, 0);
    cudaStreamWaitEvent(s2, evF, 0);
    hist_kernel<<<edge_blocks, 256, 0, s2>>>(edge_index, E);
    scan1_kernel<<<nb, 256, 0, s2>>>(N);
    scan2_kernel<<<1, 512, 0, s2>>>(nb);
    scan3_kernel<<<(N + 256) / 256, 256, 0, s2>>>(N, E);
    fill_kernel<<<edge_blocks, 256, 0, s2>>>(edge_index, E);
    cudaEventRecord(evFill, s2);
    eagg_tail_kernel<<<warp8_blocks, 256, 0, s2>>>(edge_feature, N);   // concurrent with gather
    cudaEventRecord(evEagg, s2);

    // ---- main stream: weight prep + layer-1 pre-GEMM (H16 output) ----
    prep_all_kernel<<<(106496 + 255) / 256, 256>>>(c1_pre_W, c2_pre_W,
                                                   c1_msg_W, c1_msg_b,
                                                   c2_msg_W, c2_msg_b,
                                                   Bpre1, Bpre2, Bpost1, Bpost2);
    gemm_mma_kernel<0><<<gemm_blocks, 256, GSMEM>>>(node_feature, Bpre1, c1_pre_b, H16, N);

    // ---- join 1: CSR arrays ready -> gather (concurrent with eagg on s2) ----
    cudaStreamWaitEvent(0, evFill, 0);
    gather_agg_kernel<<<warp8_blocks, 256>>>(N);

    // ---- join 2: TAIL ready -> fused postGEMM1 + preGEMM2 (H16 overwritten) ----
    cudaStreamWaitEvent(0, evEagg, 0);
    gemm_fused_kernel<<<gemm_blocks, 256, FSMEM>>>(Bpost1, Bpre2, c2_pre_b, N);

    // layer 2 rest (MODE 2: stitched, NO relu — final output X fp32)
    gather_agg_kernel<<<warp8_blocks, 256>>>(N);
    gemm_mma_kernel<2><<<gemm_blocks, 256, GSMEM>>>(nullptr, Bpost2, nullptr, X, N);

    head_kernel<<<(Q + 7) / 8, 256>>>(X, eli, lp_W, lp_b, out, Q);
}

// round 17
// speedup vs baseline: 1.5981x; 1.0127x over previous
#include <cuda_runtime.h>
#include <cuda_fp16.h>
#include <cstdint>

#define NN 50000
#define EE 500000
#define D  128

// ---------------- device scratch (no allocation allowed) ----------------
__device__ __align__(16) uint16_t g_H16[(size_t)NN * D];  // fp16 pre-conv output
__device__ __align__(16) uint16_t g_X16[(size_t)NN * D];  // fp16 final conv output
__device__ float g_AGG[(size_t)NN * D];          // gathered neighbor sum (fp32)
__device__ float g_TAIL[(size_t)NN * 32];        // [eagg(16) | deg | 0...]
__device__ float g_DEG[NN];
__device__ int   g_cnt[NN], g_cur[NN];
__device__ int   g_off[NN + 1];
__device__ int   g_srce[EE], g_eid[EE];
__device__ int   g_bsum[512];
__device__ int   g_e64, g_q64;
// fp16 B images, fragment-paired half2 layout, 36-half (18-word) padded rows.
__device__ uint16_t g_Bpre16[2][4 * 4608];    // K=128 -> 4 chunks
__device__ uint16_t g_Bpost16[2][9 * 4608];   // K=288 -> 9 chunks

// ---------------- helpers ----------------
__device__ __forceinline__ uint32_t f2h2(float2 v) {
    uint32_t o;
    asm("cvt.rn.f16x2.f32 %0, %1, %2;" : "=r"(o) : "f"(v.y), "f"(v.x));
    return o;
}
__device__ __forceinline__ void mma_f16(float* c, uint32_t a0, uint32_t a1,
                                        uint32_t a2, uint32_t a3,
                                        uint32_t b0, uint32_t b1) {
    asm volatile(
        "mma.sync.aligned.m16n8k16.row.col.f32.f16.f16.f32 "
        "{%0,%1,%2,%3}, {%4,%5,%6,%7}, {%8,%9}, {%0,%1,%2,%3};"
        : "+f"(c[0]), "+f"(c[1]), "+f"(c[2]), "+f"(c[3])
        : "r"(a0), "r"(a1), "r"(a2), "r"(a3), "r"(b0), "r"(b1));
}
__device__ __forceinline__ void cpa16(uint32_t dst, const void* src, int sz) {
    asm volatile("cp.async.cg.shared.global [%0], [%1], 16, %2;"
                 :: "r"(dst), "l"(src), "r"(sz) : "memory");
}
#define CP_COMMIT() asm volatile("cp.async.commit_group;" ::: "memory")
#define CP_WAIT1()  asm volatile("cp.async.wait_group 1;" ::: "memory")

// ---------------- fused detect (warp-parallel) + zero ----------------
__global__ void detect_zero_kernel(const int* __restrict__ ei, const int* __restrict__ eli, int n) {
    int i = blockIdx.x * blockDim.x + threadIdx.x;
    if (i < n) { g_cnt[i] = 0; g_cur[i] = 0; }
    if (blockIdx.x == 0 && threadIdx.x < 32) {
        int lane = threadIdx.x;
        int a = 0, b = 0;
        #pragma unroll
        for (int j = 0; j < 4; j++) {
            a |= ei[2 * (lane * 4 + j) + 1];
            b |= eli[2 * (lane * 4 + j) + 1];
        }
        unsigned ba = __ballot_sync(0xffffffffu, a != 0);
        unsigned bb = __ballot_sync(0xffffffffu, b != 0);
        if (lane == 0) {
            g_e64 = (ba == 0) ? 1 : 0;
            g_q64 = (bb == 0) ? 1 : 0;
        }
    }
}

// ---------------- fused B-image prep (fp16) ----------------
__device__ __forceinline__ void prep_one(const float* W, const float* bias,
                                         uint16_t* img, int K_eff, int idx) {
    int n = idx & 127;
    int k = idx >> 7;
    float v = 0.f;
    if (k < K_eff) v = W[(size_t)k * 128 + n];
    else if (k == K_eff && bias != nullptr) v = bias[n];
    __half h = __float2half_rn(v);
    img[(size_t)(k >> 5) * 4608 + n * 36 + (k & 31)] = *(uint16_t*)&h;
}
__global__ void prep_all_kernel(const float* W1, const float* W2,
                                const float* W3, const float* b3,
                                const float* W4, const float* b4,
                                uint16_t* img1, uint16_t* img2,
                                uint16_t* img3, uint16_t* img4) {
    int idx = blockIdx.x * blockDim.x + threadIdx.x;
    if (idx < 16384)       prep_one(W1, nullptr, img1, 128, idx);
    else if (idx < 32768)  prep_one(W2, nullptr, img2, 128, idx - 16384);
    else if (idx < 69632)  prep_one(W3, b3, img3, 272, idx - 32768);
    else if (idx < 106496) prep_one(W4, b4, img4, 272, idx - 69632);
}

// ---------------- CSR build ----------------
__global__ void hist_kernel(const void* __restrict__ ei, int E) {
    int e = blockIdx.x * blockDim.x + threadIdx.x;
    if (e >= E) return;
    int d = g_e64 ? (int)((const long long*)ei)[(size_t)E + e] : ((const int*)ei)[(size_t)E + e];
    atomicAdd(&g_cnt[d], 1);
}
__global__ void scan1_kernel(int n) {
    __shared__ int s[256];
    int idx = blockIdx.x * 256 + threadIdx.x;
    int v = (idx < n) ? g_cnt[idx] : 0;
    s[threadIdx.x] = v; __syncthreads();
    #pragma unroll
    for (int o = 1; o < 256; o <<= 1) {
        int t = (threadIdx.x >= o) ? s[threadIdx.x - o] : 0;
        __syncthreads(); s[threadIdx.x] += t; __syncthreads();
    }
    if (idx < n) g_off[idx] = s[threadIdx.x] - v;
    if (threadIdx.x == 255) g_bsum[blockIdx.x] = s[255];
}
// Fused scan2+scan3: each block computes its own prefix of g_bsum (one warp,
// multi-block — avoids the measured grid=1 single-CTA penalty), then applies.
__global__ void scan23_kernel(int n, int E) {
    __shared__ int sbase;
    const int bid = blockIdx.x;
    if (threadIdx.x < 32) {
        int lane = threadIdx.x;
        int s = 0;
        for (int j = lane; j < bid; j += 32) s += g_bsum[j];
        #pragma unroll
        for (int o = 16; o; o >>= 1) s += __shfl_down_sync(0xffffffffu, s, o);
        if (lane == 0) sbase = s;
    }
    __syncthreads();
    int idx = bid * 256 + threadIdx.x;
    if (idx < n) {
        g_off[idx] += sbase;
        g_DEG[idx] = (float)g_cnt[idx];
    }
    if (idx == n) g_off[n] = E;
}
__global__ void fill_kernel(const void* __restrict__ ei, int E) {
    int e = blockIdx.x * blockDim.x + threadIdx.x;
    if (e >= E) return;
    int s, d;
    if (g_e64) {
        s = (int)((const long long*)ei)[e];
        d = (int)((const long long*)ei)[(size_t)E + e];
    } else {
        s = ((const int*)ei)[e];
        d = ((const int*)ei)[(size_t)E + e];
    }
    int pos = g_off[d] + atomicAdd(&g_cur[d], 1);
    g_srce[pos] = s;
    g_eid[pos]  = e;
}
// eagg + TAIL pack: TAIL[w][0..15]=eagg, [16]=deg, [17..31]=0
__global__ __launch_bounds__(256)
void eagg_tail_kernel(const float* __restrict__ ef, int n) {
    int w = (blockIdx.x * blockDim.x + threadIdx.x) >> 5;
    int lane = threadIdx.x & 31;
    if (w >= n) return;
    int rs = g_off[w], re = g_off[w + 1];
    float acc = 0.f;
    if (lane < 16) {
        for (int j = rs; j < re; j++) {
            int e = __ldg(&g_eid[j]);
            acc += __ldg(ef + (size_t)e * 16 + lane);
        }
    } else if (lane == 16) {
        acc = g_DEG[w];
    }
    g_TAIL[(size_t)w * 32 + lane] = acc;
}

// ---------------- aggregation gather (atomic-free, fp16 H reads) ----------
__global__ __launch_bounds__(256)
void gather_agg_kernel(int n) {
    int w = (blockIdx.x * blockDim.x + threadIdx.x) >> 5;
    int lane = threadIdx.x & 31;
    if (w >= n) return;
    int rs = g_off[w], re = g_off[w + 1];
    float4 a0 = make_float4(0.f, 0.f, 0.f, 0.f);
    float4 a1 = make_float4(0.f, 0.f, 0.f, 0.f);
    const uint16_t* base = g_H16 + lane * 4;   // 4 halves per lane
    int j = rs;
    for (; j + 1 < re; j += 2) {
        int s0 = __ldg(&g_srce[j]), s1 = __ldg(&g_srce[j + 1]);
        uint2 u0 = *(const uint2*)(base + (size_t)s0 * 128);
        uint2 u1 = *(const uint2*)(base + (size_t)s1 * 128);
        float2 p0 = __half22float2(*(__half2*)&u0.x);
        float2 p1 = __half22float2(*(__half2*)&u0.y);
        float2 q0 = __half22float2(*(__half2*)&u1.x);
        float2 q1 = __half22float2(*(__half2*)&u1.y);
        a0.x += p0.x; a0.y += p0.y; a0.z += p1.x; a0.w += p1.y;
        a1.x += q0.x; a1.y += q0.y; a1.z += q1.x; a1.w += q1.y;
    }
    if (j < re) {
        int s0 = __ldg(&g_srce[j]);
        uint2 u0 = *(const uint2*)(base + (size_t)s0 * 128);
        float2 p0 = __half22float2(*(__half2*)&u0.x);
        float2 p1 = __half22float2(*(__half2*)&u0.y);
        a0.x += p0.x; a0.y += p0.y; a0.z += p1.x; a0.w += p1.y;
    }
    a0.x += a1.x; a0.y += a1.y; a0.z += a1.z; a0.w += a1.w;
    *(float4*)(g_AGG + (size_t)w * 128 + lane * 4) = a0;
}

// ---------------- fp16 mma GEMM, cp.async double-buffered ----------------
// SMEM (floats): Asb0 [0,4608) Asb1 [4608,9216), B: Bs0 at 9216, Bs1 at 11520.
#define GSMEM (13824 * 4)                            // 55296 B
#define FSMEM ((13824 + 4 * 2560) * 4)               // 96256 B (+ fp16 X tile)

// MODE 0: plain fp32 A (K=128), bias+relu, fp16 output (H16).
// MODE 2: stitched K=288 from H16|AGG|TAIL, deg-scale after chunk 3,
//         NO relu, fp16 output (X16, final layer).
template <int MODE>
__device__ __forceinline__ void stage_chunk(const float* __restrict__ A,
                                            const uint16_t* __restrict__ Bimg,
                                            float* AsBuf, uint32_t* BsBuf,
                                            int c, int block_row, int n, int tid) {
    const int k0 = c * 32;
    if (MODE != 0 && k0 < 128) {
        // fp16 tile: 128 rows x 64 B data in 80 B smem rows (512 x 16B)
        #pragma unroll
        for (int l = 0; l < 2; l++) {
            int i = tid + l * 256;
            int r = i >> 2, j = i & 3;
            int grow = block_row + r;
            uint32_t dst = (uint32_t)__cvta_generic_to_shared((char*)AsBuf + r * 80 + j * 16);
            cpa16(dst, (const char*)g_H16 + (size_t)grow * 256 + k0 * 2 + j * 16,
                  grow < n ? 16 : 0);
        }
    } else {
        const float* srcbase;
        int stride, off;
        if (MODE == 0)     { srcbase = A;      stride = 128; off = k0; }
        else if (k0 < 256) { srcbase = g_AGG;  stride = 128; off = k0 - 128; }
        else               { srcbase = g_TAIL; stride = 32;  off = 0; }
        #pragma unroll
        for (int l = 0; l < 4; l++) {
            int i = tid + l * 256;                 // 1024 = 128 rows x 8 float4
            int r = i >> 3, kq = (i & 7) << 2;
            int grow = block_row + r;
            uint32_t dst = (uint32_t)__cvta_generic_to_shared(AsBuf + r * 36 + kq);
            cpa16(dst, srcbase + (size_t)grow * stride + off + kq, grow < n ? 16 : 0);
        }
    }
    // B chunk: 4608 halves = 9216 B = 576 x 16B
    const float4* bsrc = (const float4*)(Bimg + (size_t)c * 4608);
    #pragma unroll
    for (int l = 0; l < 3; l++) {
        int i = tid + l * 256;
        if (i < 576) {
            uint32_t dst = (uint32_t)__cvta_generic_to_shared((float4*)BsBuf + i);
            cpa16(dst, bsrc + i, 16);
        }
    }
}
__device__ __forceinline__ void stage_b_only(const uint16_t* __restrict__ Bimg,
                                             uint32_t* BsBuf, int c, int tid) {
    const float4* bsrc = (const float4*)(Bimg + (size_t)c * 4608);
    #pragma unroll
    for (int l = 0; l < 3; l++) {
        int i = tid + l * 256;
        if (i < 576) {
            uint32_t dst = (uint32_t)__cvta_generic_to_shared((float4*)BsBuf + i);
            cpa16(dst, bsrc + i, 16);
        }
    }
}

// fp32-A chunk: convert at fragment load.
__device__ __forceinline__ void mma_chunk(float acc[4][4][4], const float* Asrc,
                                          int astride, int akoff, const uint32_t* Bs,
                                          int wr, int wc, int g, int tg) {
    #pragma unroll
    for (int ks = 0; ks < 2; ks++) {
        const int kb = akoff + ks * 16;
        uint32_t bfr[4][2];
        #pragma unroll
        for (int u = 0; u < 4; u++) {
            const int nn = wc + u * 8 + g;
            bfr[u][0] = Bs[nn * 18 + ks * 8 + tg];
            bfr[u][1] = Bs[nn * 18 + ks * 8 + tg + 4];
        }
        #pragma unroll
        for (int t = 0; t < 4; t++) {
            const int r0 = wr + t * 16 + g, r1 = r0 + 8;
            float2 x0 = *(const float2*)&Asrc[r0 * astride + kb + 2 * tg];
            float2 x1 = *(const float2*)&Asrc[r1 * astride + kb + 2 * tg];
            float2 x2 = *(const float2*)&Asrc[r0 * astride + kb + 2 * tg + 8];
            float2 x3 = *(const float2*)&Asrc[r1 * astride + kb + 2 * tg + 8];
            uint32_t a0 = f2h2(x0), a1 = f2h2(x1), a2 = f2h2(x2), a3 = f2h2(x3);
            #pragma unroll
            for (int u = 0; u < 4; u++)
                mma_f16(acc[t][u], a0, a1, a2, a3, bfr[u][0], bfr[u][1]);
        }
    }
}
// fp16-A chunk: direct packed loads (rows of 20 words; word j = k pair (2j,2j+1)).
__device__ __forceinline__ void mma_chunk_h(float acc[4][4][4], const uint32_t* As,
                                            const uint32_t* Bs,
                                            int wr, int wc, int g, int tg) {
    #pragma unroll
    for (int ks = 0; ks < 2; ks++) {
        uint32_t bfr[4][2];
        #pragma unroll
        for (int u = 0; u < 4; u++) {
            const int nn = wc + u * 8 + g;
            bfr[u][0] = Bs[nn * 18 + ks * 8 + tg];
            bfr[u][1] = Bs[nn * 18 + ks * 8 + tg + 4];
        }
        #pragma unroll
        for (int t = 0; t < 4; t++) {
            const int r0 = wr + t * 16 + g, r1 = r0 + 8;
            uint32_t a0 = As[r0 * 20 + ks * 8 + tg];
            uint32_t a1 = As[r1 * 20 + ks * 8 + tg];
            uint32_t a2 = As[r0 * 20 + ks * 8 + tg + 4];
            uint32_t a3 = As[r1 * 20 + ks * 8 + tg + 4];
            #pragma unroll
            for (int u = 0; u < 4; u++)
                mma_f16(acc[t][u], a0, a1, a2, a3, bfr[u][0], bfr[u][1]);
        }
    }
}

// deg*(H·Wi) == (deg⊙H)·Wi
__device__ __forceinline__ void scale_acc_deg(float acc[4][4][4], int block_row,
                                              int wr, int g, int n) {
    #pragma unroll
    for (int t = 0; t < 4; t++) {
        const int r0 = block_row + wr + t * 16 + g, r1 = r0 + 8;
        const float d0 = (r0 < n) ? g_DEG[r0] : 0.f;
        const float d1 = (r1 < n) ? g_DEG[r1] : 0.f;
        #pragma unroll
        for (int u = 0; u < 4; u++) {
            acc[t][u][0] *= d0; acc[t][u][1] *= d0;
            acc[t][u][2] *= d1; acc[t][u][3] *= d1;
        }
    }
}

template <int MODE>
__global__ __launch_bounds__(256, 2)
void gemm_mma_kernel(const float* __restrict__ A, const uint16_t* __restrict__ Bimg,
                     const float* __restrict__ bias, uint16_t* __restrict__ Cout, int n) {
    extern __shared__ __align__(16) float sm[];
    float* Asb[2] = { sm, sm + 4608 };
    uint32_t* Bsb[2] = { (uint32_t*)(sm + 9216), (uint32_t*)(sm + 11520) };
    const int tid = threadIdx.x, lane = tid & 31, wid = tid >> 5;
    const int g = lane >> 2, tg = lane & 3;
    const int wr = (wid & 1) * 64, wc = (wid >> 1) * 32;
    const int block_row = blockIdx.x * 128;
    const int CHUNKS = (MODE == 0) ? 4 : 9;

    float acc[4][4][4];
    #pragma unroll
    for (int t = 0; t < 4; t++)
        #pragma unroll
        for (int u = 0; u < 4; u++)
            #pragma unroll
            for (int v = 0; v < 4; v++) acc[t][u][v] = 0.f;

    stage_chunk<MODE>(A, Bimg, Asb[0], Bsb[0], 0, block_row, n, tid);
    CP_COMMIT();

    for (int c = 0; c < CHUNKS; c++) {
        const int cur = c & 1;
        if (c + 1 < CHUNKS)
            stage_chunk<MODE>(A, Bimg, Asb[(c + 1) & 1], Bsb[(c + 1) & 1],
                              c + 1, block_row, n, tid);
        CP_COMMIT();
        CP_WAIT1();
        __syncthreads();
        if (MODE != 0 && c < 4)
            mma_chunk_h(acc, (const uint32_t*)Asb[cur], Bsb[cur], wr, wc, g, tg);
        else
            mma_chunk(acc, Asb[cur], 36, 0, Bsb[cur], wr, wc, g, tg);
        if (MODE != 0 && c == 3)
            scale_acc_deg(acc, block_row, wr, g, n);
        __syncthreads();
    }
    // ---- epilogue (fp16 output for both modes) ----
    #pragma unroll
    for (int t = 0; t < 4; t++) {
        const int r0 = block_row + wr + t * 16 + g, r1 = r0 + 8;
        #pragma unroll
        for (int u = 0; u < 4; u++) {
            const int col = wc + u * 8 + tg * 2;
            float2 v0 = make_float2(acc[t][u][0], acc[t][u][1]);
            float2 v1 = make_float2(acc[t][u][2], acc[t][u][3]);
            if (MODE == 0) {
                float2 b2 = *(const float2*)(bias + col);
                v0.x = fmaxf(v0.x + b2.x, 0.f); v0.y = fmaxf(v0.y + b2.y, 0.f);
                v1.x = fmaxf(v1.x + b2.x, 0.f); v1.y = fmaxf(v1.y + b2.y, 0.f);
            }
            // MODE 2: raw accumulator (final layer, no relu)
            if (r0 < n) *(uint32_t*)((char*)Cout + (size_t)r0 * 256 + col * 2) = f2h2(v0);
            if (r1 < n) *(uint32_t*)((char*)Cout + (size_t)r1 * 256 + col * 2) = f2h2(v1);
        }
    }
}

// ---------------- FUSED: postGEMM layer1 + preGEMM layer2 ----
// GEMM1: stitched K=288 (H16|AGG|TAIL, deg-scale after chunk 3) -> relu ->
//        fp16 X tile in staged-chunk layout (4 chunks x 128 rows x 20 words).
// GEMM2: X tile (fp16 SMEM) x Bpre2, +bias2, relu -> g_H16 (layer-2 H).
__global__ __launch_bounds__(256, 2)
void gemm_fused_kernel(const uint16_t* __restrict__ Bimg1, const uint16_t* __restrict__ Bimg2,
                       const float* __restrict__ bias2, int n) {
    extern __shared__ __align__(16) float sm[];
    float* Asb[2] = { sm, sm + 4608 };
    uint32_t* Bsb[2] = { (uint32_t*)(sm + 9216), (uint32_t*)(sm + 11520) };
    uint32_t* Xt = (uint32_t*)(sm + 13824);   // 4 chunks x 2560 words (fp16 pairs)
    const int tid = threadIdx.x, lane = tid & 31, wid = tid >> 5;
    const int g = lane >> 2, tg = lane & 3;
    const int wr = (wid & 1) * 64, wc = (wid >> 1) * 32;
    const int block_row = blockIdx.x * 128;

    float acc[4][4][4];
    #pragma unroll
    for (int t = 0; t < 4; t++)
        #pragma unroll
        for (int u = 0; u < 4; u++)
            #pragma unroll
            for (int v = 0; v < 4; v++) acc[t][u][v] = 0.f;

    // ================= GEMM 1 (stitched K=288) =================
    stage_chunk<1>(nullptr, Bimg1, Asb[0], Bsb[0], 0, block_row, n, tid);
    CP_COMMIT();
    for (int c = 0; c < 9; c++) {
        const int cur = c & 1;
        if (c + 1 < 9)
            stage_chunk<1>(nullptr, Bimg1, Asb[(c + 1) & 1], Bsb[(c + 1) & 1],
                           c + 1, block_row, n, tid);
        CP_COMMIT();
        CP_WAIT1();
        __syncthreads();
        if (c < 4)
            mma_chunk_h(acc, (const uint32_t*)Asb[cur], Bsb[cur], wr, wc, g, tg);
        else
            mma_chunk(acc, Asb[cur], 36, 0, Bsb[cur], wr, wc, g, tg);
        if (c == 3)
            scale_acc_deg(acc, block_row, wr, g, n);
        __syncthreads();
    }
    // prefetch GEMM2's first B chunk while writing the X tile
    stage_b_only(Bimg2, Bsb[0], 0, tid);
    CP_COMMIT();
    // epilogue1 -> fp16 X tile (relu); word (col&31)>>1 of chunk col>>5
    #pragma unroll
    for (int t = 0; t < 4; t++) {
        const int r0 = wr + t * 16 + g, r1 = r0 + 8;
        #pragma unroll
        for (int u = 0; u < 4; u++) {
            const int col = wc + u * 8 + tg * 2;
            const int base = (col >> 5) * 2560 + ((col & 31) >> 1);
            float2 v0 = make_float2(fmaxf(acc[t][u][0], 0.f), fmaxf(acc[t][u][1], 0.f));
            float2 v1 = make_float2(fmaxf(acc[t][u][2], 0.f), fmaxf(acc[t][u][3], 0.f));
            Xt[base + r0 * 20] = f2h2(v0);
            Xt[base + r1 * 20] = f2h2(v1);
        }
    }
    // ================= GEMM 2 (fp16 X tile) =================
    #pragma unroll
    for (int t = 0; t < 4; t++)
        #pragma unroll
        for (int u = 0; u < 4; u++)
            #pragma unroll
            for (int v = 0; v < 4; v++) acc[t][u][v] = 0.f;
    __syncthreads();                        // X tile visible to all warps
    for (int c = 0; c < 4; c++) {
        const int cur = c & 1;
        if (c + 1 < 4)
            stage_b_only(Bimg2, Bsb[(c + 1) & 1], c + 1, tid);
        CP_COMMIT();
        CP_WAIT1();
        __syncthreads();
        mma_chunk_h(acc, Xt + c * 2560, Bsb[cur], wr, wc, g, tg);
        __syncthreads();
    }
    // epilogue2: relu(acc + bias2) -> g_H16 (fp16)
    #pragma unroll
    for (int t = 0; t < 4; t++) {
        const int r0 = block_row + wr + t * 16 + g, r1 = r0 + 8;
        #pragma unroll
        for (int u = 0; u < 4; u++) {
            const int col = wc + u * 8 + tg * 2;
            float2 b2 = *(const float2*)(bias2 + col);
            float2 v0, v1;
            v0.x = fmaxf(acc[t][u][0] + b2.x, 0.f); v0.y = fmaxf(acc[t][u][1] + b2.y, 0.f);
            v1.x = fmaxf(acc[t][u][2] + b2.x, 0.f); v1.y = fmaxf(acc[t][u][3] + b2.y, 0.f);
            if (r0 < n) *(uint32_t*)((char*)g_H16 + (size_t)r0 * 256 + col * 2) = f2h2(v0);
            if (r1 < n) *(uint32_t*)((char*)g_H16 + (size_t)r1 * 256 + col * 2) = f2h2(v1);
        }
    }
}

// ---------------- link-prediction head (fp16 X reads) ----------------
__global__ __launch_bounds__(256)
void head_kernel(const void* __restrict__ eli,
                 const float* __restrict__ lpW, const float* __restrict__ lpb,
                 float* __restrict__ out, int Q) {
    int w = (blockIdx.x * blockDim.x + threadIdx.x) >> 5;
    int lane = threadIdx.x & 31;
    if (w >= Q) return;
    float2 wa[4], wb[4];
    #pragma unroll
    for (int i = 0; i < 4; i++) {
        wa[i] = *(const float2*)(lpW + (size_t)(4 * lane + i) * 2);
        wb[i] = *(const float2*)(lpW + (size_t)(128 + 4 * lane + i) * 2);
    }
    int i0 = 0, i1 = 0;
    if (lane == 0) {
        if (g_q64) {
            i0 = (int)((const long long*)eli)[w];
            i1 = (int)((const long long*)eli)[(size_t)Q + w];
        } else {
            i0 = ((const int*)eli)[w];
            i1 = ((const int*)eli)[(size_t)Q + w];
        }
    }
    i0 = __shfl_sync(0xffffffffu, i0, 0);
    i1 = __shfl_sync(0xffffffffu, i1, 0);
    const uint16_t* base = g_X16 + lane * 4;
    uint2 ua = *(const uint2*)(base + (size_t)i0 * 128);
    uint2 ub = *(const uint2*)(base + (size_t)i1 * 128);
    float2 a01 = __half22float2(*(__half2*)&ua.x);
    float2 a23 = __half22float2(*(__half2*)&ua.y);
    float2 b01 = __half22float2(*(__half2*)&ub.x);
    float2 b23 = __half22float2(*(__half2*)&ub.y);
    float p0 = a01.x * wa[0].x + a01.y * wa[1].x + a23.x * wa[2].x + a23.y * wa[3].x
             + b01.x * wb[0].x + b01.y * wb[1].x + b23.x * wb[2].x + b23.y * wb[3].x;
    float p1 = a01.x * wa[0].y + a01.y * wa[1].y + a23.x * wa[2].y + a23.y * wa[3].y
             + b01.x * wb[0].y + b01.y * wb[1].y + b23.x * wb[2].y + b23.y * wb[3].y;
    #pragma unroll
    for (int off = 16; off; off >>= 1) {
        p0 += __shfl_down_sync(0xffffffffu, p0, off);
        p1 += __shfl_down_sync(0xffffffffu, p1, off);
    }
    if (lane == 0) {
        out[(size_t)2 * w + 0] = p0 + lpb[0];
        out[(size_t)2 * w + 1] = p1 + lpb[1];
    }
}

// ---------------- launch ----------------
extern "C" void kernel_launch(void* const* d_in, const int* in_sizes, int n_in,
                              void* d_out, int out_size) {
    const float* node_feature = (const float*)d_in[0];
    const void*  edge_index   = d_in[1];
    const float* edge_feature = (const float*)d_in[2];
    const void*  eli          = d_in[3];
    const float* c1_pre_W = (const float*)d_in[4];
    const float* c1_pre_b = (const float*)d_in[5];
    const float* c1_msg_W = (const float*)d_in[6];
    const float* c1_msg_b = (const float*)d_in[7];
    const float* c2_pre_W = (const float*)d_in[8];
    const float* c2_pre_b = (const float*)d_in[9];
    const float* c2_msg_W = (const float*)d_in[10];
    const float* c2_msg_b = (const float*)d_in[11];
    const float* lp_W     = (const float*)d_in[12];
    const float* lp_b     = (const float*)d_in[13];
    float* out = (float*)d_out;

    const int N = in_sizes[0] / D;
    const int E = in_sizes[1] / 2;
    const int Q = in_sizes[3] / 2;

    uint16_t *H16, *X16, *Bpre, *Bpost;
    cudaGetSymbolAddress((void**)&H16, g_H16);
    cudaGetSymbolAddress((void**)&X16, g_X16);
    cudaGetSymbolAddress((void**)&Bpre, g_Bpre16);
    cudaGetSymbolAddress((void**)&Bpost, g_Bpost16);
    uint16_t* Bpre1  = Bpre;
    uint16_t* Bpre2  = Bpre + 4 * 4608;
    uint16_t* Bpost1 = Bpost;
    uint16_t* Bpost2 = Bpost + 9 * 4608;

    static int init_done = 0;
    static cudaStream_t s2;
    static cudaEvent_t evF, evFill, evEagg;
    if (!init_done) {
        cudaFuncSetAttribute(gemm_mma_kernel<0>, cudaFuncAttributeMaxDynamicSharedMemorySize, GSMEM);
        cudaFuncSetAttribute(gemm_mma_kernel<2>, cudaFuncAttributeMaxDynamicSharedMemorySize, GSMEM);
        cudaFuncSetAttribute(gemm_fused_kernel, cudaFuncAttributeMaxDynamicSharedMemorySize, FSMEM);
        cudaStreamCreateWithFlags(&s2, cudaStreamNonBlocking);
        cudaEventCreateWithFlags(&evF, cudaEventDisableTiming);
        cudaEventCreateWithFlags(&evFill, cudaEventDisableTiming);
        cudaEventCreateWithFlags(&evEagg, cudaEventDisableTiming);
        init_done = 1;
    }

    const int gemm_blocks  = (N + 127) / 128;
    const int warp8_blocks = (N + 7) / 8;
    const int edge_blocks  = (E + 255) / 256;
    const int nb = (N + 255) / 256;

    // root: zero counters + dtype detect
    detect_zero_kernel<<<nb, 256>>>((const int*)edge_index, (const int*)eli, N);

    // ---- fork: CSR build on side stream ----
    cudaEventRecord(evF, 0);
    cudaStreamWaitEvent(s2, evF, 0);
    hist_kernel<<<edge_blocks, 256, 0, s2>>>(edge_index, E);
    scan1_kernel<<<nb, 256, 0, s2>>>(N);
    scan23_kernel<<<nb, 256, 0, s2>>>(N, E);
    fill_kernel<<<edge_blocks, 256, 0, s2>>>(edge_index, E);
    cudaEventRecord(evFill, s2);
    eagg_tail_kernel<<<warp8_blocks, 256, 0, s2>>>(edge_feature, N);   // concurrent with gather
    cudaEventRecord(evEagg, s2);

    // ---- main stream: weight prep + layer-1 pre-GEMM (H16 output) ----
    prep_all_kernel<<<(106496 + 255) / 256, 256>>>(c1_pre_W, c2_pre_W,
                                                   c1_msg_W, c1_msg_b,
                                                   c2_msg_W, c2_msg_b,
                                                   Bpre1, Bpre2, Bpost1, Bpost2);
    gemm_mma_kernel<0><<<gemm_blocks, 256, GSMEM>>>(node_feature, Bpre1, c1_pre_b, H16, N);

    // ---- join 1: CSR arrays ready -> gather (concurrent with eagg on s2) ----
    cudaStreamWaitEvent(0, evFill, 0);
    gather_agg_kernel<<<warp8_blocks, 256>>>(N);

    // ---- join 2: TAIL ready -> fused postGEMM1 + preGEMM2 (H16 overwritten) ----
    cudaStreamWaitEvent(0, evEagg, 0);
    gemm_fused_kernel<<<gemm_blocks, 256, FSMEM>>>(Bpost1, Bpre2, c2_pre_b, N);

    // layer 2 rest (MODE 2: stitched, NO relu — final output X16 fp16)
    gather_agg_kernel<<<warp8_blocks, 256>>>(N);
    gemm_mma_kernel<2><<<gemm_blocks, 256, GSMEM>>>(nullptr, Bpost2, nullptr, X16, N);

    head_kernel<<<(Q + 7) / 8, 256>>>(eli, lp_W, lp_b, out, Q);
}